// round 3
// baseline (speedup 1.0000x reference)
#include <cuda_runtime.h>

// Problem constants (fixed by the dataset)
#define N_NODES 12288
#define F_DIMV  512
#define H_DIMV  64
#define E_MAX   393216

typedef unsigned long long ull;

// ---------------- f32x2 packed helpers (FFMA2 path) ----------------
__device__ __forceinline__ void ffma2(ull& d, ull a, ull b) {
    asm("fma.rn.f32x2 %0, %1, %2, %0;" : "+l"(d) : "l"(a), "l"(b));
}
__device__ __forceinline__ ull pack2(float x, float y) {
    ull r;
    asm("mov.b64 %0, {%1, %2};" : "=l"(r) : "f"(x), "f"(y));
    return r;
}
__device__ __forceinline__ float2 unpack2(ull v) {
    float2 r;
    asm("mov.b64 {%0, %1}, %2;" : "=f"(r.x), "=f"(r.y) : "l"(v));
    return r;
}

// ---------------- scratch (no allocations allowed) ----------------
__device__ float g_m[N_NODES * H_DIMV];      // transformed feats pre-aggregation
__device__ float g_x[N_NODES * H_DIMV];      // encoder layer 1 out
__device__ float g_x2[N_NODES * H_DIMV];     // encoder layer 2 out
__device__ float g_xa[N_NODES * H_DIMV];     // attr decoder hidden
__device__ float g_aggxa[N_NODES * H_DIMV];  // agg(xa)
__device__ float g_s[N_NODES * H_DIMV];      // structure embedding
__device__ int   g_deg[N_NODES];
__device__ int   g_off[N_NODES + 1];
__device__ int   g_cur[N_NODES];
__device__ int   g_csr[E_MAX];

// ---------------- CSR build ----------------
__global__ void k_zero_deg() {
    int i = blockIdx.x * blockDim.x + threadIdx.x;
    if (i < N_NODES) g_deg[i] = 0;
}

__global__ void k_count(const int* __restrict__ ei, int E) {
    int e = blockIdx.x * blockDim.x + threadIdx.x;
    if (e < E) atomicAdd(&g_deg[ei[E + e]], 1);
}

// Single-block exclusive scan over 12288 counts (1024 threads x 12 items)
__global__ void k_scan() {
    __shared__ int ts[1024];
    int t = threadIdx.x;
    int base = t * 12;
    int loc[12];
    int s = 0;
#pragma unroll
    for (int i = 0; i < 12; i++) { loc[i] = s; s += g_deg[base + i]; }
    ts[t] = s;
    __syncthreads();
    for (int d = 1; d < 1024; d <<= 1) {
        int v = ts[t];
        int add = (t >= d) ? ts[t - d] : 0;
        __syncthreads();
        ts[t] = v + add;
        __syncthreads();
    }
    int prev = (t == 0) ? 0 : ts[t - 1];
#pragma unroll
    for (int i = 0; i < 12; i++) {
        int o = prev + loc[i];
        g_off[base + i] = o;
        g_cur[base + i] = o;
    }
    if (t == 1023) g_off[N_NODES] = ts[1023];
}

__global__ void k_fill(const int* __restrict__ ei, int E) {
    int e = blockIdx.x * blockDim.x + threadIdx.x;
    if (e < E) {
        int dst = ei[E + e];
        int p = atomicAdd(&g_cur[dst], 1);
        g_csr[p] = ei[e];
    }
}

// ---------------- edge aggregation: out[n] = relu(sum_{e: dst=n} m[src_e] + b)
// one warp per node, float2 per lane (64 dims). m is L2-resident (3MB).
__global__ void k_agg(const float* __restrict__ m, const float* __restrict__ bias,
                      float* __restrict__ out, int relu) {
    int w = (blockIdx.x * blockDim.x + threadIdx.x) >> 5;
    if (w >= N_NODES) return;
    int lane = threadIdx.x & 31;
    int e = g_off[w], e1 = g_off[w + 1];
    float ax = 0.f, ay = 0.f;
    for (; e + 1 < e1; e += 2) {
        int sa = g_csr[e], sb = g_csr[e + 1];
        float2 va = *(const float2*)(m + sa * 64 + 2 * lane);
        float2 vb = *(const float2*)(m + sb * 64 + 2 * lane);
        ax += va.x; ay += va.y;
        ax += vb.x; ay += vb.y;
    }
    if (e < e1) {
        float2 va = *(const float2*)(m + g_csr[e] * 64 + 2 * lane);
        ax += va.x; ay += va.y;
    }
    if (bias) { ax += bias[2 * lane]; ay += bias[2 * lane + 1]; }
    if (relu) { ax = fmaxf(ax, 0.f); ay = fmaxf(ay, 0.f); }
    float2 r; r.x = ax; r.y = ay;
    *(float2*)(out + w * 64 + 2 * lane) = r;
}

// ---------------- GEMM: Y[N,P] = X[N,K] @ W[K,P] (+bias, relu)
// 64x64 tile / block, 256 threads, 4 rows x 2 col-pairs (f32x2) per thread.
__global__ void __launch_bounds__(256)
k_gemm64(const float* __restrict__ X, const float* __restrict__ W,
         const float* __restrict__ bias, float* __restrict__ Y,
         int K, int P, int relu) {
    __shared__ __align__(16) float As[32 * 65];   // [k][row]
    __shared__ __align__(16) float Bs[32 * 66];   // [k][col], even stride for 8B loads
    int tid = threadIdx.x;
    int tx = tid & 15, ty = tid >> 4;
    int rbase = blockIdx.x * 64, cbase = blockIdx.y * 64;

    ull acc[4][2];
#pragma unroll
    for (int i = 0; i < 4; i++)
#pragma unroll
        for (int j = 0; j < 2; j++) acc[i][j] = pack2(0.f, 0.f);

    for (int kc = 0; kc < K; kc += 32) {
        __syncthreads();
#pragma unroll
        for (int i = 0; i < 8; i++) {                  // 2048 A floats
            int idx = tid + i * 256;
            int k = idx & 31, row = idx >> 5;
            As[k * 65 + row] = X[(size_t)(rbase + row) * K + kc + k];
        }
#pragma unroll
        for (int i = 0; i < 8; i++) {                  // 2048 B floats
            int idx = tid + i * 256;
            int k = idx >> 6, c = idx & 63;
            Bs[k * 66 + c] = W[(size_t)(kc + k) * P + cbase + c];
        }
        __syncthreads();
#pragma unroll 8
        for (int k = 0; k < 32; k++) {
            float a[4]; ull a2[4]; ull b2[2];
#pragma unroll
            for (int i = 0; i < 4; i++) a[i] = As[k * 65 + ty + i * 16];
#pragma unroll
            for (int j = 0; j < 2; j++)
                b2[j] = *(const ull*)(&Bs[k * 66 + 2 * tx + 32 * j]);
#pragma unroll
            for (int i = 0; i < 4; i++) a2[i] = pack2(a[i], a[i]);
#pragma unroll
            for (int i = 0; i < 4; i++)
#pragma unroll
                for (int j = 0; j < 2; j++) ffma2(acc[i][j], a2[i], b2[j]);
        }
    }

#pragma unroll
    for (int i = 0; i < 4; i++) {
        int r = rbase + ty + i * 16;
#pragma unroll
        for (int j = 0; j < 2; j++) {
            int c = cbase + 2 * tx + 32 * j;
            float2 v = unpack2(acc[i][j]);
            if (bias) { v.x += bias[c]; v.y += bias[c + 1]; }
            if (relu) { v.x = fmaxf(v.x, 0.f); v.y = fmaxf(v.y, 0.f); }
            *(float2*)(&Y[(size_t)r * P + c]) = v;
        }
    }
}

// ---------------- C = S @ S^T, symmetric: upper-triangular tiles with FFMA2,
// mirror through an smem transpose stage (coalesced writes).
__global__ void __launch_bounds__(256, 2)
k_sst(const float* __restrict__ S, float* __restrict__ C) {
    int bx = blockIdx.x, by = blockIdx.y;     // bx = col tile, by = row tile
    if (by > bx) return;
    __shared__ __align__(16) float sm[2 * 32 * 130];
    float* As = sm;                           // [32][130]
    float* Bs = sm + 32 * 130;                // [32][130]
    int tid = threadIdx.x;
    int tx = tid & 15, ty = tid >> 4;
    int rbase = by * 128, cbase = bx * 128;
    const size_t NN = (size_t)N_NODES;

    ull acc[8][4];                            // rows ty+16i, col-pairs (2tx+32j, +1)
#pragma unroll
    for (int i = 0; i < 8; i++)
#pragma unroll
        for (int j = 0; j < 4; j++) acc[i][j] = pack2(0.f, 0.f);

    for (int kc = 0; kc < 64; kc += 32) {
        __syncthreads();
#pragma unroll
        for (int i = 0; i < 16; i++) {        // 4096 floats each
            int idx = tid + i * 256;
            int k = idx & 31, row = idx >> 5;
            As[k * 130 + row] = S[(size_t)(rbase + row) * 64 + kc + k];
            Bs[k * 130 + row] = S[(size_t)(cbase + row) * 64 + kc + k];
        }
        __syncthreads();
#pragma unroll 8
        for (int k = 0; k < 32; k++) {
            float a[8]; ull a2[8]; ull b2[4];
#pragma unroll
            for (int i = 0; i < 8; i++) a[i] = As[k * 130 + ty + i * 16];
#pragma unroll
            for (int j = 0; j < 4; j++)
                b2[j] = *(const ull*)(&Bs[k * 130 + 2 * tx + 32 * j]);
#pragma unroll
            for (int i = 0; i < 8; i++) a2[i] = pack2(a[i], a[i]);
#pragma unroll
            for (int i = 0; i < 8; i++)
#pragma unroll
                for (int j = 0; j < 4; j++) ffma2(acc[i][j], a2[i], b2[j]);
        }
    }

    // direct (upper) tile write, vectorized float2
#pragma unroll
    for (int i = 0; i < 8; i++) {
        size_t r = (size_t)(rbase + ty + i * 16);
#pragma unroll
        for (int j = 0; j < 4; j++) {
            float2 v = unpack2(acc[i][j]);
            *(float2*)(&C[r * NN + cbase + 2 * tx + 32 * j]) = v;
        }
    }

    if (by == bx) return;

    // mirror (lower) tile: stage transpose through smem, two 64-col passes.
    // Ts layout [cl][r] stride 129 (odd -> conflict-free scalar stores).
    float* Ts = sm;
    for (int p = 0; p < 2; p++) {
        __syncthreads();
#pragma unroll
        for (int i = 0; i < 8; i++)
#pragma unroll
            for (int jj = 0; jj < 2; jj++) {
                int j = 2 * p + jj;
                int cl = 2 * tx + 32 * jj;     // local col within pass
                float2 v = unpack2(acc[i][j]);
                int r = ty + i * 16;
                Ts[cl * 129 + r] = v.x;
                Ts[(cl + 1) * 129 + r] = v.y;
            }
        __syncthreads();
#pragma unroll
        for (int q = 0; q < 32; q++) {
            int lin = tid + q * 256;           // 8192 floats
            int r = lin & 127, cl = lin >> 7;
            C[(size_t)(cbase + p * 64 + cl) * NN + rbase + r] = Ts[cl * 129 + r];
        }
    }
}

// ---------------- launch ----------------
static float* symf(const void* sym) {
    void* p = nullptr;
    cudaGetSymbolAddress(&p, sym);
    return (float*)p;
}

extern "C" void kernel_launch(void* const* d_in, const int* in_sizes, int n_in,
                              void* d_out, int out_size) {
    const float* h   = (const float*)d_in[0];
    const int*   ei  = (const int*)d_in[1];
    const float* W1  = (const float*)d_in[2];
    const float* b1  = (const float*)d_in[3];
    const float* W2  = (const float*)d_in[4];
    const float* b2  = (const float*)d_in[5];
    const float* Wa1 = (const float*)d_in[6];
    const float* ba1 = (const float*)d_in[7];
    const float* Wa2 = (const float*)d_in[8];
    const float* ba2 = (const float*)d_in[9];
    const float* Ws  = (const float*)d_in[10];
    const float* bs  = (const float*)d_in[11];
    float* out = (float*)d_out;
    int E = in_sizes[1] / 2;

    float* m     = symf(g_m);
    float* x     = symf(g_x);
    float* x2    = symf(g_x2);
    float* xa    = symf(g_xa);
    float* aggxa = symf(g_aggxa);
    float* s     = symf(g_s);

    float* out_xhat = out + (size_t)N_NODES * (size_t)N_NODES;

    int eb = (E + 255) / 256;

    // CSR build (by dst)
    k_zero_deg<<<(N_NODES + 255) / 256, 256>>>();
    k_count<<<eb, 256>>>(ei, E);
    k_scan<<<1, 1024>>>();
    k_fill<<<eb, 256>>>(ei, E);

    // encoder layer 1: x = relu(agg(h @ W1) + b1)
    k_gemm64<<<dim3(192, 1), 256>>>(h, W1, nullptr, m, 512, 64, 0);
    k_agg<<<1536, 256>>>(m, b1, x, 1);
    // encoder layer 2: x2 = relu(agg(x @ W2) + b2)
    k_gemm64<<<dim3(192, 1), 256>>>(x, W2, nullptr, m, 64, 64, 0);
    k_agg<<<1536, 256>>>(m, b2, x2, 1);
    // attribute decoder hidden: xa = relu(agg(x2 @ Wa1) + ba1)
    k_gemm64<<<dim3(192, 1), 256>>>(x2, Wa1, nullptr, m, 64, 64, 0);
    k_agg<<<1536, 256>>>(m, ba1, xa, 1);
    // attribute decoder out: x_hat = relu(agg(xa) @ Wa2 + ba2)   [agg/linear commute]
    k_agg<<<1536, 256>>>(xa, nullptr, aggxa, 0);
    k_gemm64<<<dim3(192, 8), 256>>>(aggxa, Wa2, ba2, out_xhat, 64, 512, 1);
    // structure decoder: s = relu(agg(x2 @ Ws) + bs); struct = s @ s^T
    k_gemm64<<<dim3(192, 1), 256>>>(x2, Ws, nullptr, m, 64, 64, 0);
    k_agg<<<1536, 256>>>(m, bs, s, 1);
    k_sst<<<dim3(96, 96), 256>>>(s, out);
}

// round 6
// speedup vs baseline: 1.0378x; 1.0378x over previous
#include <cuda_runtime.h>
#include <cuda_bf16.h>
#include <cstdint>

// Problem constants (fixed by the dataset)
#define N_NODES 12288
#define F_DIMV  512
#define H_DIMV  64
#define E_MAX   393216
#define NTILE   96          // 12288 / 128

typedef unsigned long long ull;

// ---------------- f32x2 packed helpers (kept from passing kernel) ----------------
__device__ __forceinline__ void ffma2(ull& d, ull a, ull b) {
    asm("fma.rn.f32x2 %0, %1, %2, %0;" : "+l"(d) : "l"(a), "l"(b));
}
__device__ __forceinline__ ull pack2(float x, float y) {
    ull r;
    asm("mov.b64 %0, {%1, %2};" : "=l"(r) : "f"(x), "f"(y));
    return r;
}
__device__ __forceinline__ float2 unpack2(ull v) {
    float2 r;
    asm("mov.b64 {%0, %1}, %2;" : "=f"(r.x), "=f"(r.y) : "l"(v));
    return r;
}

// ---------------- warp MMA helpers (sm_80+ baseline, compile OK for compute_103) ----
__device__ __forceinline__ uint32_t smem_u32(const void* p) {
    uint32_t a;
    asm("{ .reg .u64 t; cvta.to.shared.u64 t, %1; cvt.u32.u64 %0, t; }"
        : "=r"(a) : "l"(p));
    return a;
}
__device__ __forceinline__ void ldsm_x4(uint32_t& r0, uint32_t& r1, uint32_t& r2,
                                        uint32_t& r3, uint32_t addr) {
    asm volatile("ldmatrix.sync.aligned.m8n8.x4.shared.b16 {%0,%1,%2,%3}, [%4];"
                 : "=r"(r0), "=r"(r1), "=r"(r2), "=r"(r3) : "r"(addr));
}
__device__ __forceinline__ void ldsm_x2(uint32_t& r0, uint32_t& r1, uint32_t addr) {
    asm volatile("ldmatrix.sync.aligned.m8n8.x2.shared.b16 {%0,%1}, [%2];"
                 : "=r"(r0), "=r"(r1) : "r"(addr));
}
__device__ __forceinline__ void mma_bf16(float d[4], uint32_t a0, uint32_t a1,
                                         uint32_t a2, uint32_t a3,
                                         uint32_t b0, uint32_t b1) {
    asm volatile(
        "mma.sync.aligned.m16n8k16.row.col.f32.bf16.bf16.f32 "
        "{%0,%1,%2,%3}, {%4,%5,%6,%7}, {%8,%9}, {%0,%1,%2,%3};"
        : "+f"(d[0]), "+f"(d[1]), "+f"(d[2]), "+f"(d[3])
        : "r"(a0), "r"(a1), "r"(a2), "r"(a3), "r"(b0), "r"(b1));
}

// ---------------- scratch (no allocations allowed) ----------------
__device__ float g_m[N_NODES * H_DIMV];
__device__ float g_x[N_NODES * H_DIMV];
__device__ float g_x2[N_NODES * H_DIMV];
__device__ float g_xa[N_NODES * H_DIMV];
__device__ float g_aggxa[N_NODES * H_DIMV];
__device__ float g_s[N_NODES * H_DIMV];
__device__ int   g_deg[N_NODES];
__device__ int   g_off[N_NODES + 1];
__device__ int   g_cur[N_NODES];
__device__ int   g_csr[E_MAX];

// ---------------- CSR build ----------------
__global__ void k_zero_deg() {
    int i = blockIdx.x * blockDim.x + threadIdx.x;
    if (i < N_NODES) g_deg[i] = 0;
}

__global__ void k_count(const int* __restrict__ ei, int E) {
    int e = blockIdx.x * blockDim.x + threadIdx.x;
    if (e < E) atomicAdd(&g_deg[ei[E + e]], 1);
}

__global__ void k_scan() {
    __shared__ int ts[1024];
    int t = threadIdx.x;
    int base = t * 12;
    int loc[12];
    int s = 0;
#pragma unroll
    for (int i = 0; i < 12; i++) { loc[i] = s; s += g_deg[base + i]; }
    ts[t] = s;
    __syncthreads();
    for (int d = 1; d < 1024; d <<= 1) {
        int v = ts[t];
        int add = (t >= d) ? ts[t - d] : 0;
        __syncthreads();
        ts[t] = v + add;
        __syncthreads();
    }
    int prev = (t == 0) ? 0 : ts[t - 1];
#pragma unroll
    for (int i = 0; i < 12; i++) {
        int o = prev + loc[i];
        g_off[base + i] = o;
        g_cur[base + i] = o;
    }
    if (t == 1023) g_off[N_NODES] = ts[1023];
}

__global__ void k_fill(const int* __restrict__ ei, int E) {
    int e = blockIdx.x * blockDim.x + threadIdx.x;
    if (e < E) {
        int dst = ei[E + e];
        int p = atomicAdd(&g_cur[dst], 1);
        g_csr[p] = ei[e];
    }
}

// ---------------- edge aggregation ----------------
__global__ void k_agg(const float* __restrict__ m, const float* __restrict__ bias,
                      float* __restrict__ out, int relu) {
    int w = (blockIdx.x * blockDim.x + threadIdx.x) >> 5;
    if (w >= N_NODES) return;
    int lane = threadIdx.x & 31;
    int e = g_off[w], e1 = g_off[w + 1];
    float ax = 0.f, ay = 0.f;
    for (; e + 1 < e1; e += 2) {
        int sa = g_csr[e], sb = g_csr[e + 1];
        float2 va = *(const float2*)(m + sa * 64 + 2 * lane);
        float2 vb = *(const float2*)(m + sb * 64 + 2 * lane);
        ax += va.x; ay += va.y;
        ax += vb.x; ay += vb.y;
    }
    if (e < e1) {
        float2 va = *(const float2*)(m + g_csr[e] * 64 + 2 * lane);
        ax += va.x; ay += va.y;
    }
    if (bias) { ax += bias[2 * lane]; ay += bias[2 * lane + 1]; }
    if (relu) { ax = fmaxf(ax, 0.f); ay = fmaxf(ay, 0.f); }
    float2 r; r.x = ax; r.y = ay;
    *(float2*)(out + w * 64 + 2 * lane) = r;
}

// ---------------- GEMM: Y[N,P] = X[N,K] @ W[K,P] (+bias, relu) ----------------
__global__ void __launch_bounds__(256)
k_gemm64(const float* __restrict__ X, const float* __restrict__ W,
         const float* __restrict__ bias, float* __restrict__ Y,
         int K, int P, int relu) {
    __shared__ __align__(16) float As[32 * 65];
    __shared__ __align__(16) float Bs[32 * 66];
    int tid = threadIdx.x;
    int tx = tid & 15, ty = tid >> 4;
    int rbase = blockIdx.x * 64, cbase = blockIdx.y * 64;

    ull acc[4][2];
#pragma unroll
    for (int i = 0; i < 4; i++)
#pragma unroll
        for (int j = 0; j < 2; j++) acc[i][j] = pack2(0.f, 0.f);

    for (int kc = 0; kc < K; kc += 32) {
        __syncthreads();
#pragma unroll
        for (int i = 0; i < 8; i++) {
            int idx = tid + i * 256;
            int k = idx & 31, row = idx >> 5;
            As[k * 65 + row] = X[(size_t)(rbase + row) * K + kc + k];
        }
#pragma unroll
        for (int i = 0; i < 8; i++) {
            int idx = tid + i * 256;
            int k = idx >> 6, c = idx & 63;
            Bs[k * 66 + c] = W[(size_t)(kc + k) * P + cbase + c];
        }
        __syncthreads();
#pragma unroll 8
        for (int k = 0; k < 32; k++) {
            float a[4]; ull a2[4]; ull b2[2];
#pragma unroll
            for (int i = 0; i < 4; i++) a[i] = As[k * 65 + ty + i * 16];
#pragma unroll
            for (int j = 0; j < 2; j++)
                b2[j] = *(const ull*)(&Bs[k * 66 + 2 * tx + 32 * j]);
#pragma unroll
            for (int i = 0; i < 4; i++) a2[i] = pack2(a[i], a[i]);
#pragma unroll
            for (int i = 0; i < 4; i++)
#pragma unroll
                for (int j = 0; j < 2; j++) ffma2(acc[i][j], a2[i], b2[j]);
        }
    }

#pragma unroll
    for (int i = 0; i < 4; i++) {
        int r = rbase + ty + i * 16;
#pragma unroll
        for (int j = 0; j < 2; j++) {
            int c = cbase + 2 * tx + 32 * j;
            float2 v = unpack2(acc[i][j]);
            if (bias) { v.x += bias[c]; v.y += bias[c + 1]; }
            if (relu) { v.x = fmaxf(v.x, 0.f); v.y = fmaxf(v.y, 0.f); }
            *(float2*)(&Y[(size_t)r * P + c]) = v;
        }
    }
}

// ---------------- C = S @ S^T via warp HMMA, split-bf16 (hi+lo) ----------------
// Per 128x128 upper-triangular tile:
//   operands in smem as bf16 [128 rows x 64 k], padded stride TS=72 elems
//   (144B row stride -> ldmatrix conflict-free).
//   8 warps = 4 row-groups (32 rows) x 2 col-halves (64 cols).
//   Per warp: 192 HMMA.16816 = (HiHi + HiLo + LoHi) over 4 k16-chunks x 8 n-tiles.
//   Direct tile written straight from fragments (8B quad-contiguous stores);
//   mirror tile staged transposed in (dead) operand smem, then float4 stores.
#define TS 72
#define SM_AHI  0
#define SM_ALO  18432
#define SM_BHI  36864
#define SM_BLO  55296
#define SM_SST_TOTAL 73728

__device__ __forceinline__ void conv_tile(const float* __restrict__ S, int rbase,
                                          __nv_bfloat16* hi, __nv_bfloat16* lo,
                                          int tid) {
    int row = tid >> 1;
    int kh = (tid & 1) * 32;
    const float4* src = (const float4*)(S + (size_t)(rbase + row) * 64 + kh);
    __nv_bfloat16* hp = hi + row * TS + kh;
    __nv_bfloat16* lp = lo + row * TS + kh;
#pragma unroll
    for (int j = 0; j < 8; j++) {
        float4 v = src[j];
        __nv_bfloat162 h01, h23, l01, l23;
        h01.x = __float2bfloat16(v.x);
        h01.y = __float2bfloat16(v.y);
        h23.x = __float2bfloat16(v.z);
        h23.y = __float2bfloat16(v.w);
        l01.x = __float2bfloat16(v.x - __bfloat162float(h01.x));
        l01.y = __float2bfloat16(v.y - __bfloat162float(h01.y));
        l23.x = __float2bfloat16(v.z - __bfloat162float(h23.x));
        l23.y = __float2bfloat16(v.w - __bfloat162float(h23.y));
        *(__nv_bfloat162*)(hp + 4 * j)     = h01;
        *(__nv_bfloat162*)(hp + 4 * j + 2) = h23;
        *(__nv_bfloat162*)(lp + 4 * j)     = l01;
        *(__nv_bfloat162*)(lp + 4 * j + 2) = l23;
    }
}

__global__ void __launch_bounds__(256)
k_sst_mma(const float* __restrict__ S, float* __restrict__ C) {
    int bx = blockIdx.x, by = blockIdx.y;
    if (by > bx) return;
    bool diag = (bx == by);

    extern __shared__ __align__(16) char smem[];
    __nv_bfloat16* Ahi = (__nv_bfloat16*)(smem + SM_AHI);
    __nv_bfloat16* Alo = (__nv_bfloat16*)(smem + SM_ALO);
    __nv_bfloat16* Bhi = (__nv_bfloat16*)(smem + SM_BHI);
    __nv_bfloat16* Blo = (__nv_bfloat16*)(smem + SM_BLO);

    int tid = threadIdx.x;
    int wid = tid >> 5;
    int lane = tid & 31;
    const size_t NN = (size_t)N_NODES;

    conv_tile(S, by * 128, Ahi, Alo, tid);
    if (!diag) conv_tile(S, bx * 128, Bhi, Blo, tid);
    __syncthreads();

    uint32_t aHI = smem_u32(Ahi), aLO = smem_u32(Alo);
    uint32_t bHI = diag ? aHI : smem_u32(Bhi);
    uint32_t bLO = diag ? aLO : smem_u32(Blo);

    int r0 = (wid >> 1) * 32;     // warp's row base within tile
    int n0 = (wid & 1) * 64;      // warp's col base within tile

    // per-lane ldmatrix address components
    int lr = lane & 7, ls = lane >> 3;
    uint32_t a_off = (uint32_t)((((ls & 1) * 8 + lr) * TS + (ls >> 1) * 8) * 2);
    uint32_t b_off = (uint32_t)((lr * TS + (ls & 1) * 8) * 2);

    float acc[8][2][4];
#pragma unroll
    for (int nt = 0; nt < 8; nt++)
#pragma unroll
        for (int rf = 0; rf < 2; rf++)
#pragma unroll
            for (int q = 0; q < 4; q++) acc[nt][rf][q] = 0.f;

#pragma unroll
    for (int ks = 0; ks < 4; ks++) {
        uint32_t koff = (uint32_t)(ks * 16 * 2);
        uint32_t ar0 = (uint32_t)(r0 * TS * 2) + koff + a_off;
        uint32_t ar1 = ar0 + (uint32_t)(16 * TS * 2);
        uint32_t h00, h01, h02, h03, h10, h11, h12, h13;
        uint32_t l00, l01, l02, l03, l10, l11, l12, l13;
        ldsm_x4(h00, h01, h02, h03, aHI + ar0);
        ldsm_x4(h10, h11, h12, h13, aHI + ar1);
        ldsm_x4(l00, l01, l02, l03, aLO + ar0);
        ldsm_x4(l10, l11, l12, l13, aLO + ar1);
#pragma unroll
        for (int nt = 0; nt < 8; nt++) {
            uint32_t boffn = (uint32_t)((n0 + nt * 8) * TS * 2) + koff + b_off;
            uint32_t bh0, bh1, bl0, bl1;
            ldsm_x2(bh0, bh1, bHI + boffn);
            ldsm_x2(bl0, bl1, bLO + boffn);
            mma_bf16(acc[nt][0], h00, h01, h02, h03, bh0, bh1);   // HiHi
            mma_bf16(acc[nt][1], h10, h11, h12, h13, bh0, bh1);
            mma_bf16(acc[nt][0], h00, h01, h02, h03, bl0, bl1);   // HiLo
            mma_bf16(acc[nt][1], h10, h11, h12, h13, bl0, bl1);
            mma_bf16(acc[nt][0], l00, l01, l02, l03, bh0, bh1);   // LoHi
            mma_bf16(acc[nt][1], l10, l11, l12, l13, bh0, bh1);
        }
    }

    // ---- direct (upper) tile: straight from fragments ----
    int gid = lane >> 2, tig = lane & 3;
    int rbase = by * 128, cbase = bx * 128;
#pragma unroll
    for (int rf = 0; rf < 2; rf++) {
        int rowa = rbase + r0 + 16 * rf + gid;
#pragma unroll
        for (int nt = 0; nt < 8; nt++) {
            int col = cbase + n0 + 8 * nt + 2 * tig;
            float2 v0; v0.x = acc[nt][rf][0]; v0.y = acc[nt][rf][1];
            float2 v1; v1.x = acc[nt][rf][2]; v1.y = acc[nt][rf][3];
            *(float2*)(&C[(size_t)rowa * NN + col]) = v0;
            *(float2*)(&C[(size_t)(rowa + 8) * NN + col]) = v1;
        }
    }

    if (diag) return;

    // ---- mirror (lower) tile: transpose via smem stage (operands are dead) ----
    __syncthreads();                      // all warps done reading operand smem
    float* Ts = (float*)smem;             // [128 cols][129] floats = 66048 B
#pragma unroll
    for (int rf = 0; rf < 2; rf++) {
        int rl = r0 + 16 * rf + gid;
#pragma unroll
        for (int nt = 0; nt < 8; nt++) {
            int cl = n0 + 8 * nt + 2 * tig;
            Ts[cl * 129 + rl]            = acc[nt][rf][0];
            Ts[(cl + 1) * 129 + rl]      = acc[nt][rf][1];
            Ts[cl * 129 + rl + 8]        = acc[nt][rf][2];
            Ts[(cl + 1) * 129 + rl + 8]  = acc[nt][rf][3];
        }
    }
    __syncthreads();
#pragma unroll
    for (int i = 0; i < 16; i++) {
        int lin = tid + i * 256;          // 4096 float4s
        int c = lin >> 5, q = (lin & 31) * 4;
        float4 v;
        v.x = Ts[c * 129 + q];
        v.y = Ts[c * 129 + q + 1];
        v.z = Ts[c * 129 + q + 2];
        v.w = Ts[c * 129 + q + 3];
        *(float4*)(&C[(size_t)(cbase + c) * NN + rbase + q]) = v;
    }
}

// ---------------- launch ----------------
static float* symf(const void* sym) {
    void* p = nullptr;
    cudaGetSymbolAddress(&p, sym);
    return (float*)p;
}

extern "C" void kernel_launch(void* const* d_in, const int* in_sizes, int n_in,
                              void* d_out, int out_size) {
    const float* h   = (const float*)d_in[0];
    const int*   ei  = (const int*)d_in[1];
    const float* W1  = (const float*)d_in[2];
    const float* b1  = (const float*)d_in[3];
    const float* W2  = (const float*)d_in[4];
    const float* b2  = (const float*)d_in[5];
    const float* Wa1 = (const float*)d_in[6];
    const float* ba1 = (const float*)d_in[7];
    const float* Wa2 = (const float*)d_in[8];
    const float* ba2 = (const float*)d_in[9];
    const float* Ws  = (const float*)d_in[10];
    const float* bs  = (const float*)d_in[11];
    float* out = (float*)d_out;
    int E = in_sizes[1] / 2;

    float* m     = symf(g_m);
    float* x     = symf(g_x);
    float* x2    = symf(g_x2);
    float* xa    = symf(g_xa);
    float* aggxa = symf(g_aggxa);
    float* s     = symf(g_s);

    float* out_xhat = out + (size_t)N_NODES * (size_t)N_NODES;

    int eb = (E + 255) / 256;

    static int smem_set = 0;
    if (!smem_set) {
        cudaFuncSetAttribute(k_sst_mma, cudaFuncAttributeMaxDynamicSharedMemorySize,
                             SM_SST_TOTAL);
        smem_set = 1;
    }

    // CSR build (by dst)
    k_zero_deg<<<(N_NODES + 255) / 256, 256>>>();
    k_count<<<eb, 256>>>(ei, E);
    k_scan<<<1, 1024>>>();
    k_fill<<<eb, 256>>>(ei, E);

    // encoder layer 1: x = relu(agg(h @ W1) + b1)
    k_gemm64<<<dim3(192, 1), 256>>>(h, W1, nullptr, m, 512, 64, 0);
    k_agg<<<1536, 256>>>(m, b1, x, 1);
    // encoder layer 2: x2 = relu(agg(x @ W2) + b2)
    k_gemm64<<<dim3(192, 1), 256>>>(x, W2, nullptr, m, 64, 64, 0);
    k_agg<<<1536, 256>>>(m, b2, x2, 1);
    // attribute decoder hidden: xa = relu(agg(x2 @ Wa1) + ba1)
    k_gemm64<<<dim3(192, 1), 256>>>(x2, Wa1, nullptr, m, 64, 64, 0);
    k_agg<<<1536, 256>>>(m, ba1, xa, 1);
    // attribute decoder out: x_hat = relu(agg(xa) @ Wa2 + ba2)
    k_agg<<<1536, 256>>>(xa, nullptr, aggxa, 0);
    k_gemm64<<<dim3(192, 8), 256>>>(aggxa, Wa2, ba2, out_xhat, 64, 512, 1);
    // structure decoder: s = relu(agg(x2 @ Ws) + bs); struct = s @ s^T (HMMA)
    k_gemm64<<<dim3(192, 1), 256>>>(x2, Ws, nullptr, m, 64, 64, 0);
    k_agg<<<1536, 256>>>(m, bs, s, 1);
    k_sst_mma<<<dim3(NTILE, NTILE), 256, SM_SST_TOTAL>>>(s, out);
}

// round 7
// speedup vs baseline: 1.0938x; 1.0540x over previous
#include <cuda_runtime.h>
#include <cuda_fp16.h>
#include <cstdint>

// Problem constants (fixed by the dataset)
#define N_NODES 12288
#define F_DIMV  512
#define H_DIMV  64
#define E_MAX   393216
#define NTILE   96          // 12288 / 128

typedef unsigned long long ull;

// ---------------- f32x2 packed helpers ----------------
__device__ __forceinline__ void ffma2(ull& d, ull a, ull b) {
    asm("fma.rn.f32x2 %0, %1, %2, %0;" : "+l"(d) : "l"(a), "l"(b));
}
__device__ __forceinline__ ull pack2(float x, float y) {
    ull r;
    asm("mov.b64 %0, {%1, %2};" : "=l"(r) : "f"(x), "f"(y));
    return r;
}
__device__ __forceinline__ float2 unpack2(ull v) {
    float2 r;
    asm("mov.b64 {%0, %1}, %2;" : "=f"(r.x), "=f"(r.y) : "l"(v));
    return r;
}

// ---------------- warp MMA helpers (sm_80+ baseline) ----------------
__device__ __forceinline__ uint32_t smem_u32(const void* p) {
    uint32_t a;
    asm("{ .reg .u64 t; cvta.to.shared.u64 t, %1; cvt.u32.u64 %0, t; }"
        : "=r"(a) : "l"(p));
    return a;
}
__device__ __forceinline__ void ldsm_x4(uint32_t& r0, uint32_t& r1, uint32_t& r2,
                                        uint32_t& r3, uint32_t addr) {
    asm volatile("ldmatrix.sync.aligned.m8n8.x4.shared.b16 {%0,%1,%2,%3}, [%4];"
                 : "=r"(r0), "=r"(r1), "=r"(r2), "=r"(r3) : "r"(addr));
}
__device__ __forceinline__ void mma_f16(float d[4], uint32_t a0, uint32_t a1,
                                        uint32_t a2, uint32_t a3,
                                        uint32_t b0, uint32_t b1) {
    asm volatile(
        "mma.sync.aligned.m16n8k16.row.col.f32.f16.f16.f32 "
        "{%0,%1,%2,%3}, {%4,%5,%6,%7}, {%8,%9}, {%0,%1,%2,%3};"
        : "+f"(d[0]), "+f"(d[1]), "+f"(d[2]), "+f"(d[3])
        : "r"(a0), "r"(a1), "r"(a2), "r"(a3), "r"(b0), "r"(b1));
}

// ---------------- scratch (no allocations allowed) ----------------
__device__ float g_m[N_NODES * H_DIMV];
__device__ float g_x[N_NODES * H_DIMV];
__device__ float g_x2[N_NODES * H_DIMV];
__device__ float g_xa[N_NODES * H_DIMV];
__device__ float g_aggxa[N_NODES * H_DIMV];
__device__ float g_s[N_NODES * H_DIMV];
__device__ int   g_deg[N_NODES];
__device__ int   g_off[N_NODES + 1];
__device__ int   g_cur[N_NODES];
__device__ int   g_csr[E_MAX];

// ---------------- CSR build ----------------
__global__ void k_zero_deg() {
    int i = blockIdx.x * blockDim.x + threadIdx.x;
    if (i < N_NODES) g_deg[i] = 0;
}

__global__ void k_count(const int* __restrict__ ei, int E) {
    int e = blockIdx.x * blockDim.x + threadIdx.x;
    if (e < E) atomicAdd(&g_deg[ei[E + e]], 1);
}

__global__ void k_scan() {
    __shared__ int ts[1024];
    int t = threadIdx.x;
    int base = t * 12;
    int loc[12];
    int s = 0;
#pragma unroll
    for (int i = 0; i < 12; i++) { loc[i] = s; s += g_deg[base + i]; }
    ts[t] = s;
    __syncthreads();
    for (int d = 1; d < 1024; d <<= 1) {
        int v = ts[t];
        int add = (t >= d) ? ts[t - d] : 0;
        __syncthreads();
        ts[t] = v + add;
        __syncthreads();
    }
    int prev = (t == 0) ? 0 : ts[t - 1];
#pragma unroll
    for (int i = 0; i < 12; i++) {
        int o = prev + loc[i];
        g_off[base + i] = o;
        g_cur[base + i] = o;
    }
    if (t == 1023) g_off[N_NODES] = ts[1023];
}

__global__ void k_fill(const int* __restrict__ ei, int E) {
    int e = blockIdx.x * blockDim.x + threadIdx.x;
    if (e < E) {
        int dst = ei[E + e];
        int p = atomicAdd(&g_cur[dst], 1);
        g_csr[p] = ei[e];
    }
}

// ---------------- edge aggregation ----------------
__global__ void k_agg(const float* __restrict__ m, const float* __restrict__ bias,
                      float* __restrict__ out, int relu) {
    int w = (blockIdx.x * blockDim.x + threadIdx.x) >> 5;
    if (w >= N_NODES) return;
    int lane = threadIdx.x & 31;
    int e = g_off[w], e1 = g_off[w + 1];
    float ax = 0.f, ay = 0.f;
    for (; e + 1 < e1; e += 2) {
        int sa = g_csr[e], sb = g_csr[e + 1];
        float2 va = *(const float2*)(m + sa * 64 + 2 * lane);
        float2 vb = *(const float2*)(m + sb * 64 + 2 * lane);
        ax += va.x; ay += va.y;
        ax += vb.x; ay += vb.y;
    }
    if (e < e1) {
        float2 va = *(const float2*)(m + g_csr[e] * 64 + 2 * lane);
        ax += va.x; ay += va.y;
    }
    if (bias) { ax += bias[2 * lane]; ay += bias[2 * lane + 1]; }
    if (relu) { ax = fmaxf(ax, 0.f); ay = fmaxf(ay, 0.f); }
    float2 r; r.x = ax; r.y = ay;
    *(float2*)(out + w * 64 + 2 * lane) = r;
}

// ---------------- GEMM: Y[N,P] = X[N,K] @ W[K,P] (+bias, relu) ----------------
__global__ void __launch_bounds__(256)
k_gemm64(const float* __restrict__ X, const float* __restrict__ W,
         const float* __restrict__ bias, float* __restrict__ Y,
         int K, int P, int relu) {
    __shared__ __align__(16) float As[32 * 65];
    __shared__ __align__(16) float Bs[32 * 66];
    int tid = threadIdx.x;
    int tx = tid & 15, ty = tid >> 4;
    int rbase = blockIdx.x * 64, cbase = blockIdx.y * 64;

    ull acc[4][2];
#pragma unroll
    for (int i = 0; i < 4; i++)
#pragma unroll
        for (int j = 0; j < 2; j++) acc[i][j] = pack2(0.f, 0.f);

    for (int kc = 0; kc < K; kc += 32) {
        __syncthreads();
#pragma unroll
        for (int i = 0; i < 8; i++) {
            int idx = tid + i * 256;
            int k = idx & 31, row = idx >> 5;
            As[k * 65 + row] = X[(size_t)(rbase + row) * K + kc + k];
        }
#pragma unroll
        for (int i = 0; i < 8; i++) {
            int idx = tid + i * 256;
            int k = idx >> 6, c = idx & 63;
            Bs[k * 66 + c] = W[(size_t)(kc + k) * P + cbase + c];
        }
        __syncthreads();
#pragma unroll 8
        for (int k = 0; k < 32; k++) {
            float a[4]; ull a2[4]; ull b2[2];
#pragma unroll
            for (int i = 0; i < 4; i++) a[i] = As[k * 65 + ty + i * 16];
#pragma unroll
            for (int j = 0; j < 2; j++)
                b2[j] = *(const ull*)(&Bs[k * 66 + 2 * tx + 32 * j]);
#pragma unroll
            for (int i = 0; i < 4; i++) a2[i] = pack2(a[i], a[i]);
#pragma unroll
            for (int i = 0; i < 4; i++)
#pragma unroll
                for (int j = 0; j < 2; j++) ffma2(acc[i][j], a2[i], b2[j]);
        }
    }

#pragma unroll
    for (int i = 0; i < 4; i++) {
        int r = rbase + ty + i * 16;
#pragma unroll
        for (int j = 0; j < 2; j++) {
            int c = cbase + 2 * tx + 32 * j;
            float2 v = unpack2(acc[i][j]);
            if (bias) { v.x += bias[c]; v.y += bias[c + 1]; }
            if (relu) { v.x = fmaxf(v.x, 0.f); v.y = fmaxf(v.y, 0.f); }
            *(float2*)(&Y[(size_t)r * P + c]) = v;
        }
    }
}

// ---------------- C = S @ S^T via single-pass fp16 HMMA ----------------
// s >= 0 (post-relu), so all products are nonnegative: elementwise rel err of
// fp16-input/fp32-accum MMA is bounded by ~2^-11 (< 5e-4), no cancellation.
// Per 128x128 upper-triangular tile: operands fp16 [128 x 64], stride TS=72
// halves (144B rows -> ldmatrix conflict-free). 8 warps = 4 row-groups x 2
// col-halves; 64 HMMA.16816/warp. Direct tile from fragments; mirror tile via
// smem transpose stage reusing operand smem.
#define TS 72
#define SM_A  0
#define SM_B  18432
#define SM_SST_TOTAL 66560    // stage 128x129 floats (66048) reuses [0..)

__device__ __forceinline__ void conv_tile_h(const float* __restrict__ S, int rbase,
                                            __half* dst, int tid) {
    int row = tid >> 1;
    int kh = (tid & 1) * 32;
    const float4* src = (const float4*)(S + (size_t)(rbase + row) * 64 + kh);
    __half* p = dst + row * TS + kh;
#pragma unroll
    for (int j = 0; j < 8; j++) {
        float4 v = src[j];
        __half2 h01, h23;
        h01.x = __float2half_rn(v.x);
        h01.y = __float2half_rn(v.y);
        h23.x = __float2half_rn(v.z);
        h23.y = __float2half_rn(v.w);
        *(__half2*)(p + 4 * j)     = h01;
        *(__half2*)(p + 4 * j + 2) = h23;
    }
}

__global__ void __launch_bounds__(256)
k_sst_mma(const float* __restrict__ S, float* __restrict__ C) {
    int bx = blockIdx.x, by = blockIdx.y;
    if (by > bx) return;
    bool diag = (bx == by);

    extern __shared__ __align__(16) char smem[];
    __half* Ah = (__half*)(smem + SM_A);
    __half* Bh = (__half*)(smem + SM_B);

    int tid = threadIdx.x;
    int wid = tid >> 5;
    int lane = tid & 31;
    const size_t NN = (size_t)N_NODES;

    conv_tile_h(S, by * 128, Ah, tid);
    if (!diag) conv_tile_h(S, bx * 128, Bh, tid);
    __syncthreads();

    uint32_t aB = smem_u32(Ah);
    uint32_t bB = diag ? aB : smem_u32(Bh);

    int r0 = (wid >> 1) * 32;     // warp's row base within tile
    int n0 = (wid & 1) * 64;      // warp's col base within tile

    int lr = lane & 7, ls = lane >> 3;
    // A x4: matrices (m0-7,k0-7)(m8-15,k0-7)(m0-7,k8-15)(m8-15,k8-15)
    uint32_t a_off = (uint32_t)((((ls & 1) * 8 + lr) * TS + (ls >> 1) * 8) * 2);
    // B x4 spanning two n-tiles: (n0-7,k0-7)(n0-7,k8-15)(n8-15,k0-7)(n8-15,k8-15)
    uint32_t b_off = (uint32_t)(((lr + (ls >> 1) * 8) * TS + (ls & 1) * 8) * 2);

    float acc[8][2][4];
#pragma unroll
    for (int nt = 0; nt < 8; nt++)
#pragma unroll
        for (int rf = 0; rf < 2; rf++)
#pragma unroll
            for (int q = 0; q < 4; q++) acc[nt][rf][q] = 0.f;

#pragma unroll
    for (int ks = 0; ks < 4; ks++) {
        uint32_t koff = (uint32_t)(ks * 16 * 2);
        uint32_t ar0 = (uint32_t)(r0 * TS * 2) + koff + a_off;
        uint32_t ar1 = ar0 + (uint32_t)(16 * TS * 2);
        uint32_t a00, a01, a02, a03, a10, a11, a12, a13;
        ldsm_x4(a00, a01, a02, a03, aB + ar0);
        ldsm_x4(a10, a11, a12, a13, aB + ar1);
#pragma unroll
        for (int np = 0; np < 4; np++) {        // nt pairs
            uint32_t bb = (uint32_t)((n0 + np * 16) * TS * 2) + koff + b_off;
            uint32_t b0, b1, b2, b3;
            ldsm_x4(b0, b1, b2, b3, bB + bb);
            mma_f16(acc[2 * np][0],     a00, a01, a02, a03, b0, b1);
            mma_f16(acc[2 * np][1],     a10, a11, a12, a13, b0, b1);
            mma_f16(acc[2 * np + 1][0], a00, a01, a02, a03, b2, b3);
            mma_f16(acc[2 * np + 1][1], a10, a11, a12, a13, b2, b3);
        }
    }

    // ---- direct (upper) tile: straight from fragments ----
    int gid = lane >> 2, tig = lane & 3;
    int rbase = by * 128, cbase = bx * 128;
#pragma unroll
    for (int rf = 0; rf < 2; rf++) {
        int rowa = rbase + r0 + 16 * rf + gid;
#pragma unroll
        for (int nt = 0; nt < 8; nt++) {
            int col = cbase + n0 + 8 * nt + 2 * tig;
            float2 v0; v0.x = acc[nt][rf][0]; v0.y = acc[nt][rf][1];
            float2 v1; v1.x = acc[nt][rf][2]; v1.y = acc[nt][rf][3];
            *(float2*)(&C[(size_t)rowa * NN + col]) = v0;
            *(float2*)(&C[(size_t)(rowa + 8) * NN + col]) = v1;
        }
    }

    if (diag) return;

    // ---- mirror (lower) tile: transpose via smem stage (operands dead) ----
    __syncthreads();
    float* Ts = (float*)smem;             // [128 cols][129] floats
#pragma unroll
    for (int rf = 0; rf < 2; rf++) {
        int rl = r0 + 16 * rf + gid;
#pragma unroll
        for (int nt = 0; nt < 8; nt++) {
            int cl = n0 + 8 * nt + 2 * tig;
            Ts[cl * 129 + rl]            = acc[nt][rf][0];
            Ts[(cl + 1) * 129 + rl]      = acc[nt][rf][1];
            Ts[cl * 129 + rl + 8]        = acc[nt][rf][2];
            Ts[(cl + 1) * 129 + rl + 8]  = acc[nt][rf][3];
        }
    }
    __syncthreads();
#pragma unroll
    for (int i = 0; i < 16; i++) {
        int lin = tid + i * 256;          // 4096 float4s
        int c = lin >> 5, q = (lin & 31) * 4;
        float4 v;
        v.x = Ts[c * 129 + q];
        v.y = Ts[c * 129 + q + 1];
        v.z = Ts[c * 129 + q + 2];
        v.w = Ts[c * 129 + q + 3];
        *(float4*)(&C[(size_t)(cbase + c) * NN + rbase + q]) = v;
    }
}

// ---------------- launch ----------------
static float* symf(const void* sym) {
    void* p = nullptr;
    cudaGetSymbolAddress(&p, sym);
    return (float*)p;
}

extern "C" void kernel_launch(void* const* d_in, const int* in_sizes, int n_in,
                              void* d_out, int out_size) {
    const float* h   = (const float*)d_in[0];
    const int*   ei  = (const int*)d_in[1];
    const float* W1  = (const float*)d_in[2];
    const float* b1  = (const float*)d_in[3];
    const float* W2  = (const float*)d_in[4];
    const float* b2  = (const float*)d_in[5];
    const float* Wa1 = (const float*)d_in[6];
    const float* ba1 = (const float*)d_in[7];
    const float* Wa2 = (const float*)d_in[8];
    const float* ba2 = (const float*)d_in[9];
    const float* Ws  = (const float*)d_in[10];
    const float* bs  = (const float*)d_in[11];
    float* out = (float*)d_out;
    int E = in_sizes[1] / 2;

    float* m     = symf(g_m);
    float* x     = symf(g_x);
    float* x2    = symf(g_x2);
    float* xa    = symf(g_xa);
    float* aggxa = symf(g_aggxa);
    float* s     = symf(g_s);

    float* out_xhat = out + (size_t)N_NODES * (size_t)N_NODES;

    int eb = (E + 255) / 256;

    static int smem_set = 0;
    if (!smem_set) {
        cudaFuncSetAttribute(k_sst_mma, cudaFuncAttributeMaxDynamicSharedMemorySize,
                             SM_SST_TOTAL);
        smem_set = 1;
    }

    // CSR build (by dst)
    k_zero_deg<<<(N_NODES + 255) / 256, 256>>>();
    k_count<<<eb, 256>>>(ei, E);
    k_scan<<<1, 1024>>>();
    k_fill<<<eb, 256>>>(ei, E);

    // encoder layer 1: x = relu(agg(h @ W1) + b1)
    k_gemm64<<<dim3(192, 1), 256>>>(h, W1, nullptr, m, 512, 64, 0);
    k_agg<<<1536, 256>>>(m, b1, x, 1);
    // encoder layer 2: x2 = relu(agg(x @ W2) + b2)
    k_gemm64<<<dim3(192, 1), 256>>>(x, W2, nullptr, m, 64, 64, 0);
    k_agg<<<1536, 256>>>(m, b2, x2, 1);
    // attribute decoder hidden: xa = relu(agg(x2 @ Wa1) + ba1)
    k_gemm64<<<dim3(192, 1), 256>>>(x2, Wa1, nullptr, m, 64, 64, 0);
    k_agg<<<1536, 256>>>(m, ba1, xa, 1);
    // attribute decoder out: x_hat = relu(agg(xa) @ Wa2 + ba2)
    k_agg<<<1536, 256>>>(xa, nullptr, aggxa, 0);
    k_gemm64<<<dim3(192, 8), 256>>>(aggxa, Wa2, ba2, out_xhat, 64, 512, 1);
    // structure decoder: s = relu(agg(x2 @ Ws) + bs); struct = s @ s^T (fp16 HMMA)
    k_gemm64<<<dim3(192, 1), 256>>>(x2, Ws, nullptr, m, 64, 64, 0);
    k_agg<<<1536, 256>>>(m, bs, s, 1);
    k_sst_mma<<<dim3(NTILE, NTILE), 256, SM_SST_TOTAL>>>(s, out);
}

// round 11
// speedup vs baseline: 1.3042x; 1.1923x over previous
#include <cuda_runtime.h>
#include <cuda_fp16.h>
#include <cstdint>

// Problem constants (fixed by the dataset)
#define N_NODES 12288
#define F_DIMV  512
#define H_DIMV  64
#define E_MAX   393216
#define NTILE   96          // 12288 / 128

typedef unsigned long long ull;

// ---------------- f32x2 packed helpers ----------------
__device__ __forceinline__ void ffma2(ull& d, ull a, ull b) {
    asm("fma.rn.f32x2 %0, %1, %2, %0;" : "+l"(d) : "l"(a), "l"(b));
}
__device__ __forceinline__ ull pack2(float x, float y) {
    ull r;
    asm("mov.b64 %0, {%1, %2};" : "=l"(r) : "f"(x), "f"(y));
    return r;
}
__device__ __forceinline__ float2 unpack2(ull v) {
    float2 r;
    asm("mov.b64 {%0, %1}, %2;" : "=f"(r.x), "=f"(r.y) : "l"(v));
    return r;
}

// ---------------- warp MMA helpers (sm_80+ baseline) ----------------
__device__ __forceinline__ uint32_t smem_u32(const void* p) {
    uint32_t a;
    asm("{ .reg .u64 t; cvta.to.shared.u64 t, %1; cvt.u32.u64 %0, t; }"
        : "=r"(a) : "l"(p));
    return a;
}
__device__ __forceinline__ void ldsm_x4(uint32_t& r0, uint32_t& r1, uint32_t& r2,
                                        uint32_t& r3, uint32_t addr) {
    asm volatile("ldmatrix.sync.aligned.m8n8.x4.shared.b16 {%0,%1,%2,%3}, [%4];"
                 : "=r"(r0), "=r"(r1), "=r"(r2), "=r"(r3) : "r"(addr));
}
__device__ __forceinline__ void mma_f16(float d[4], uint32_t a0, uint32_t a1,
                                        uint32_t a2, uint32_t a3,
                                        uint32_t b0, uint32_t b1) {
    asm volatile(
        "mma.sync.aligned.m16n8k16.row.col.f32.f16.f16.f32 "
        "{%0,%1,%2,%3}, {%4,%5,%6,%7}, {%8,%9}, {%0,%1,%2,%3};"
        : "+f"(d[0]), "+f"(d[1]), "+f"(d[2]), "+f"(d[3])
        : "r"(a0), "r"(a1), "r"(a2), "r"(a3), "r"(b0), "r"(b1));
}
__device__ __forceinline__ void stcs4(float* p, float4 v) {
    asm volatile("st.global.cs.v4.f32 [%0], {%1,%2,%3,%4};"
                 :: "l"(p), "f"(v.x), "f"(v.y), "f"(v.z), "f"(v.w) : "memory");
}

// ---------------- scratch (no allocations allowed) ----------------
__device__ float  g_m[N_NODES * H_DIMV];
__device__ float  g_x[N_NODES * H_DIMV];
__device__ float  g_x2[N_NODES * H_DIMV];
__device__ float  g_xa[N_NODES * H_DIMV];
__device__ float  g_aggxa[N_NODES * H_DIMV];
__device__ __half g_sh[N_NODES * H_DIMV];      // structure embedding (fp16)
__device__ int    g_deg[N_NODES];
__device__ int    g_off[N_NODES + 1];
__device__ int    g_cur[N_NODES];
__device__ int    g_csr[E_MAX];

// ---------------- CSR build ----------------
__global__ void k_zero_deg() {
    int i = blockIdx.x * blockDim.x + threadIdx.x;
    if (i < N_NODES) g_deg[i] = 0;
}

__global__ void k_count(const int* __restrict__ ei, int E) {
    int e = blockIdx.x * blockDim.x + threadIdx.x;
    if (e < E) atomicAdd(&g_deg[ei[E + e]], 1);
}

__global__ void k_scan() {
    __shared__ int ts[1024];
    int t = threadIdx.x;
    int base = t * 12;
    int loc[12];
    int s = 0;
#pragma unroll
    for (int i = 0; i < 12; i++) { loc[i] = s; s += g_deg[base + i]; }
    ts[t] = s;
    __syncthreads();
    for (int d = 1; d < 1024; d <<= 1) {
        int v = ts[t];
        int add = (t >= d) ? ts[t - d] : 0;
        __syncthreads();
        ts[t] = v + add;
        __syncthreads();
    }
    int prev = (t == 0) ? 0 : ts[t - 1];
#pragma unroll
    for (int i = 0; i < 12; i++) {
        int o = prev + loc[i];
        g_off[base + i] = o;
        g_cur[base + i] = o;
    }
    if (t == 1023) g_off[N_NODES] = ts[1023];
}

__global__ void k_fill(const int* __restrict__ ei, int E) {
    int e = blockIdx.x * blockDim.x + threadIdx.x;
    if (e < E) {
        int dst = ei[E + e];
        int p = atomicAdd(&g_cur[dst], 1);
        g_csr[p] = ei[e];
    }
}

// ---------------- edge aggregation ----------------
// out[n] = relu(sum_{e: dst=n} m[src_e] + b). If outh != nullptr, the result
// is written as fp16 (half2) instead of fp32.
__global__ void k_agg(const float* __restrict__ m, const float* __restrict__ bias,
                      float* __restrict__ out, __half* __restrict__ outh, int relu) {
    int w = (blockIdx.x * blockDim.x + threadIdx.x) >> 5;
    if (w >= N_NODES) return;
    int lane = threadIdx.x & 31;
    int e = g_off[w], e1 = g_off[w + 1];
    float ax = 0.f, ay = 0.f;
    for (; e + 1 < e1; e += 2) {
        int sa = g_csr[e], sb = g_csr[e + 1];
        float2 va = *(const float2*)(m + sa * 64 + 2 * lane);
        float2 vb = *(const float2*)(m + sb * 64 + 2 * lane);
        ax += va.x; ay += va.y;
        ax += vb.x; ay += vb.y;
    }
    if (e < e1) {
        float2 va = *(const float2*)(m + g_csr[e] * 64 + 2 * lane);
        ax += va.x; ay += va.y;
    }
    if (bias) { ax += bias[2 * lane]; ay += bias[2 * lane + 1]; }
    if (relu) { ax = fmaxf(ax, 0.f); ay = fmaxf(ay, 0.f); }
    if (outh) {
        ((__half2*)outh)[w * 32 + lane] = __floats2half2_rn(ax, ay);
    } else {
        float2 r; r.x = ax; r.y = ay;
        *(float2*)(out + w * 64 + 2 * lane) = r;
    }
}

// ---------------- GEMM: Y[N,P] = X[N,K] @ W[K,P] (+bias, relu) ----------------
__global__ void __launch_bounds__(256)
k_gemm64(const float* __restrict__ X, const float* __restrict__ W,
         const float* __restrict__ bias, float* __restrict__ Y,
         int K, int P, int relu) {
    __shared__ __align__(16) float As[32 * 65];
    __shared__ __align__(16) float Bs[32 * 66];
    int tid = threadIdx.x;
    int tx = tid & 15, ty = tid >> 4;
    int rbase = blockIdx.x * 64, cbase = blockIdx.y * 64;

    ull acc[4][2];
#pragma unroll
    for (int i = 0; i < 4; i++)
#pragma unroll
        for (int j = 0; j < 2; j++) acc[i][j] = pack2(0.f, 0.f);

    for (int kc = 0; kc < K; kc += 32) {
        __syncthreads();
#pragma unroll
        for (int i = 0; i < 8; i++) {
            int idx = tid + i * 256;
            int k = idx & 31, row = idx >> 5;
            As[k * 65 + row] = X[(size_t)(rbase + row) * K + kc + k];
        }
#pragma unroll
        for (int i = 0; i < 8; i++) {
            int idx = tid + i * 256;
            int k = idx >> 6, c = idx & 63;
            Bs[k * 66 + c] = W[(size_t)(kc + k) * P + cbase + c];
        }
        __syncthreads();
#pragma unroll 8
        for (int k = 0; k < 32; k++) {
            float a[4]; ull a2[4]; ull b2[2];
#pragma unroll
            for (int i = 0; i < 4; i++) a[i] = As[k * 65 + ty + i * 16];
#pragma unroll
            for (int j = 0; j < 2; j++)
                b2[j] = *(const ull*)(&Bs[k * 66 + 2 * tx + 32 * j]);
#pragma unroll
            for (int i = 0; i < 4; i++) a2[i] = pack2(a[i], a[i]);
#pragma unroll
            for (int i = 0; i < 4; i++)
#pragma unroll
                for (int j = 0; j < 2; j++) ffma2(acc[i][j], a2[i], b2[j]);
        }
    }

#pragma unroll
    for (int i = 0; i < 4; i++) {
        int r = rbase + ty + i * 16;
#pragma unroll
        for (int j = 0; j < 2; j++) {
            int c = cbase + 2 * tx + 32 * j;
            float2 v = unpack2(acc[i][j]);
            if (bias) { v.x += bias[c]; v.y += bias[c + 1]; }
            if (relu) { v.x = fmaxf(v.x, 0.f); v.y = fmaxf(v.y, 0.f); }
            *(float2*)(&Y[(size_t)r * P + c]) = v;
        }
    }
}

// ---------------- C = S @ S^T via single-pass fp16 HMMA ----------------
// s >= 0 (post-relu): all products nonnegative -> fp16-input/fp32-acc MMA is
// elementwise-bounded by ~5e-4 rel err (no cancellation). 512 threads:
// warp (wid>>1) owns 16 rows, (wid&1) owns a 64-col half; 32 HMMA/warp.
// Epilogue: fragments deposit into a row-major AND a col-major smem stage
// (conflict-free mappings), then both the direct tile and the mirrored tile
// are written as fully-coalesced 512B/warp st.global.cs.v4 streams.
#define TS       72          // operand row stride in halves (144B)
#define STG_ROW  68          // row-stage stride (floats)
#define STG_COL  132         // col-stage stride (floats)
#define SM_B_OFF    18432
#define SM_COL_OFF  34816    // row-stage = [0,34816), col-stage = [34816,68608)
#define SM_SST_TOTAL 68608

__global__ void __launch_bounds__(512)
k_sst_mma(const __half* __restrict__ S, float* __restrict__ C) {
    int bx = blockIdx.x, by = blockIdx.y;
    if (by > bx) return;
    bool diag = (bx == by);

    extern __shared__ __align__(16) char smem[];
    __half* Ah = (__half*)smem;
    __half* Bh = (__half*)(smem + SM_B_OFF);
    float* srow = (float*)smem;                    // [128][STG_ROW]
    float* scol = (float*)(smem + SM_COL_OFF);     // [64][STG_COL]

    int tid = threadIdx.x;
    int wid = tid >> 5;
    int lane = tid & 31;
    const size_t NN = (size_t)N_NODES;

    // operand copy: 128 rows x 64 halves (8 int4 segs/row) = 1024 int4s.
    // 512 threads x 2 iterations.  (R10 bug: only 4 segs/row were copied.)
#pragma unroll
    for (int i = 0; i < 2; i++) {
        int idx = tid + i * 512;                   // 0..1023
        int row = idx >> 3, seg = idx & 7;
        const int4* sa = (const int4*)(S + (size_t)(by * 128 + row) * 64) + seg;
        *(int4*)(Ah + row * TS + seg * 8) = *sa;
        if (!diag) {
            const int4* sb = (const int4*)(S + (size_t)(bx * 128 + row) * 64) + seg;
            *(int4*)(Bh + row * TS + seg * 8) = *sb;
        }
    }
    __syncthreads();

    uint32_t aB = smem_u32(Ah);
    uint32_t bB = diag ? aB : smem_u32(Bh);
    int r0 = (wid >> 1) * 16;                      // warp's 16-row group
    int n0 = (wid & 1) * 64;                       // warp's col half

    int lr = lane & 7, ls = lane >> 3;
    uint32_t a_off = (uint32_t)((((ls & 1) * 8 + lr) * TS + (ls >> 1) * 8) * 2);
    uint32_t b_off = (uint32_t)(((lr + (ls >> 1) * 8) * TS + (ls & 1) * 8) * 2);

    float acc[8][4];
#pragma unroll
    for (int nt = 0; nt < 8; nt++)
#pragma unroll
        for (int q = 0; q < 4; q++) acc[nt][q] = 0.f;

#pragma unroll
    for (int ks = 0; ks < 4; ks++) {
        uint32_t koff = (uint32_t)(ks * 32);
        uint32_t a0, a1, a2, a3;
        ldsm_x4(a0, a1, a2, a3, aB + (uint32_t)(r0 * TS * 2) + koff + a_off);
#pragma unroll
        for (int np = 0; np < 4; np++) {
            uint32_t b0, b1, b2, b3;
            ldsm_x4(b0, b1, b2, b3,
                    bB + (uint32_t)((n0 + np * 16) * TS * 2) + koff + b_off);
            mma_f16(acc[2 * np],     a0, a1, a2, a3, b0, b1);
            mma_f16(acc[2 * np + 1], a0, a1, a2, a3, b2, b3);
        }
    }
    __syncthreads();                               // operands dead

    int gid = lane >> 2, tig = lane & 3;
    int rbase = by * 128, cbase = bx * 128;

#pragma unroll 1
    for (int h = 0; h < 2; h++) {
        // deposit: the 8 warps owning this col half fill both stages
        if ((wid & 1) == h) {
            int rl = r0 + gid;
#pragma unroll
            for (int nt = 0; nt < 8; nt++) {
                int cl = 8 * nt + 2 * tig;
                float2 v0; v0.x = acc[nt][0]; v0.y = acc[nt][1];
                float2 v1; v1.x = acc[nt][2]; v1.y = acc[nt][3];
                *(float2*)&srow[rl * STG_ROW + cl] = v0;
                *(float2*)&srow[(rl + 8) * STG_ROW + cl] = v1;
                if (!diag) {
                    scol[cl * STG_COL + rl]            = acc[nt][0];
                    scol[(cl + 1) * STG_COL + rl]      = acc[nt][1];
                    scol[cl * STG_COL + rl + 8]        = acc[nt][2];
                    scol[(cl + 1) * STG_COL + rl + 8]  = acc[nt][3];
                }
            }
        }
        __syncthreads();
        // direct tile half: rows 0..127, cols [cbase+64h, +64): 512B/warp stores
#pragma unroll
        for (int i = 0; i < 4; i++) {
            int lin = tid + i * 512;
            int row = lin >> 4, c4 = (lin & 15) * 4;
            float4 v = *(float4*)&srow[row * STG_ROW + c4];
            stcs4(&C[(size_t)(rbase + row) * NN + cbase + h * 64 + c4], v);
        }
        if (!diag) {
            // mirror half: rows [cbase+64h, +64), cols rbase..+127
#pragma unroll
            for (int i = 0; i < 4; i++) {
                int lin = tid + i * 512;
                int c = lin >> 5, q = (lin & 31) * 4;
                float4 v = *(float4*)&scol[c * STG_COL + q];
                stcs4(&C[(size_t)(cbase + h * 64 + c) * NN + rbase + q], v);
            }
        }
        __syncthreads();
    }
}

// ---------------- launch ----------------
static float* symf(const void* sym) {
    void* p = nullptr;
    cudaGetSymbolAddress(&p, sym);
    return (float*)p;
}

extern "C" void kernel_launch(void* const* d_in, const int* in_sizes, int n_in,
                              void* d_out, int out_size) {
    const float* h   = (const float*)d_in[0];
    const int*   ei  = (const int*)d_in[1];
    const float* W1  = (const float*)d_in[2];
    const float* b1  = (const float*)d_in[3];
    const float* W2  = (const float*)d_in[4];
    const float* b2  = (const float*)d_in[5];
    const float* Wa1 = (const float*)d_in[6];
    const float* ba1 = (const float*)d_in[7];
    const float* Wa2 = (const float*)d_in[8];
    const float* ba2 = (const float*)d_in[9];
    const float* Ws  = (const float*)d_in[10];
    const float* bs  = (const float*)d_in[11];
    float* out = (float*)d_out;
    int E = in_sizes[1] / 2;

    float*  m     = symf(g_m);
    float*  x     = symf(g_x);
    float*  x2    = symf(g_x2);
    float*  xa    = symf(g_xa);
    float*  aggxa = symf(g_aggxa);
    __half* sh    = (__half*)symf(g_sh);

    float* out_xhat = out + (size_t)N_NODES * (size_t)N_NODES;

    int eb = (E + 255) / 256;

    static int smem_set = 0;
    if (!smem_set) {
        cudaFuncSetAttribute(k_sst_mma, cudaFuncAttributeMaxDynamicSharedMemorySize,
                             SM_SST_TOTAL);
        smem_set = 1;
    }

    // CSR build (by dst)
    k_zero_deg<<<(N_NODES + 255) / 256, 256>>>();
    k_count<<<eb, 256>>>(ei, E);
    k_scan<<<1, 1024>>>();
    k_fill<<<eb, 256>>>(ei, E);

    // encoder layer 1: x = relu(agg(h @ W1) + b1)
    k_gemm64<<<dim3(192, 1), 256>>>(h, W1, nullptr, m, 512, 64, 0);
    k_agg<<<1536, 256>>>(m, b1, x, nullptr, 1);
    // encoder layer 2: x2 = relu(agg(x @ W2) + b2)
    k_gemm64<<<dim3(192, 1), 256>>>(x, W2, nullptr, m, 64, 64, 0);
    k_agg<<<1536, 256>>>(m, b2, x2, nullptr, 1);
    // structure decoder first: s = relu(agg(x2 @ Ws) + bs) in fp16; C = s s^T
    k_gemm64<<<dim3(192, 1), 256>>>(x2, Ws, nullptr, m, 64, 64, 0);
    k_agg<<<1536, 256>>>(m, bs, nullptr, sh, 1);
    k_sst_mma<<<dim3(NTILE, NTILE), 512, SM_SST_TOTAL>>>(sh, out);
    // attribute decoder: xa = relu(agg(x2 @ Wa1) + ba1)
    k_gemm64<<<dim3(192, 1), 256>>>(x2, Wa1, nullptr, m, 64, 64, 0);
    k_agg<<<1536, 256>>>(m, ba1, xa, nullptr, 1);
    // x_hat = relu(agg(xa) @ Wa2 + ba2)   [agg/linear commute]
    k_agg<<<1536, 256>>>(xa, nullptr, aggxa, nullptr, 0);
    k_gemm64<<<dim3(192, 8), 256>>>(aggxa, Wa2, ba2, out_xhat, 64, 512, 1);
}

// round 13
// speedup vs baseline: 1.4089x; 1.0803x over previous
#include <cuda_runtime.h>
#include <cuda_fp16.h>
#include <cstdint>

// Problem constants (fixed by the dataset)
#define N_NODES 12288
#define F_DIMV  512
#define H_DIMV  64
#define E_MAX   393216
#define NTILE   96          // 12288 / 128

typedef unsigned long long ull;

// ---------------- f32x2 packed helpers ----------------
__device__ __forceinline__ void ffma2(ull& d, ull a, ull b) {
    asm("fma.rn.f32x2 %0, %1, %2, %0;" : "+l"(d) : "l"(a), "l"(b));
}
__device__ __forceinline__ ull pack2(float x, float y) {
    ull r;
    asm("mov.b64 %0, {%1, %2};" : "=l"(r) : "f"(x), "f"(y));
    return r;
}
__device__ __forceinline__ float2 unpack2(ull v) {
    float2 r;
    asm("mov.b64 {%0, %1}, %2;" : "=f"(r.x), "=f"(r.y) : "l"(v));
    return r;
}

// ---------------- warp MMA helpers (sm_80+ baseline) ----------------
__device__ __forceinline__ uint32_t smem_u32(const void* p) {
    uint32_t a;
    asm("{ .reg .u64 t; cvta.to.shared.u64 t, %1; cvt.u32.u64 %0, t; }"
        : "=r"(a) : "l"(p));
    return a;
}
__device__ __forceinline__ void ldsm_x4(uint32_t& r0, uint32_t& r1, uint32_t& r2,
                                        uint32_t& r3, uint32_t addr) {
    asm volatile("ldmatrix.sync.aligned.m8n8.x4.shared.b16 {%0,%1,%2,%3}, [%4];"
                 : "=r"(r0), "=r"(r1), "=r"(r2), "=r"(r3) : "r"(addr));
}
__device__ __forceinline__ void mma_f16(float d[4], uint32_t a0, uint32_t a1,
                                        uint32_t a2, uint32_t a3,
                                        uint32_t b0, uint32_t b1) {
    asm volatile(
        "mma.sync.aligned.m16n8k16.row.col.f32.f16.f16.f32 "
        "{%0,%1,%2,%3}, {%4,%5,%6,%7}, {%8,%9}, {%0,%1,%2,%3};"
        : "+f"(d[0]), "+f"(d[1]), "+f"(d[2]), "+f"(d[3])
        : "r"(a0), "r"(a1), "r"(a2), "r"(a3), "r"(b0), "r"(b1));
}
__device__ __forceinline__ void stcs4(float* p, float4 v) {
    asm volatile("st.global.cs.v4.f32 [%0], {%1,%2,%3,%4};"
                 :: "l"(p), "f"(v.x), "f"(v.y), "f"(v.z), "f"(v.w) : "memory");
}

// ---------------- scratch (no allocations allowed) ----------------
__device__ float  g_m[N_NODES * H_DIMV];
__device__ float  g_m2[N_NODES * H_DIMV];      // attr-chain scratch (overlap-safe)
__device__ float  g_x[N_NODES * H_DIMV];
__device__ float  g_x2[N_NODES * H_DIMV];
__device__ float  g_xa[N_NODES * H_DIMV];
__device__ float  g_aggxa[N_NODES * H_DIMV];
__device__ __half g_sh[N_NODES * H_DIMV];      // structure embedding (fp16)
__device__ int    g_deg[N_NODES];
__device__ int    g_off[N_NODES + 1];
__device__ int    g_cur[N_NODES];
__device__ int    g_csr[E_MAX];

// ---------------- CSR build ----------------
__global__ void k_zero_deg() {
    int i = blockIdx.x * blockDim.x + threadIdx.x;
    if (i < N_NODES) g_deg[i] = 0;
}

__global__ void k_count(const int* __restrict__ ei, int E) {
    int e = blockIdx.x * blockDim.x + threadIdx.x;
    if (e < E) atomicAdd(&g_deg[ei[E + e]], 1);
}

__global__ void k_scan() {
    __shared__ int ts[1024];
    int t = threadIdx.x;
    int base = t * 12;
    int loc[12];
    int s = 0;
#pragma unroll
    for (int i = 0; i < 12; i++) { loc[i] = s; s += g_deg[base + i]; }
    ts[t] = s;
    __syncthreads();
    for (int d = 1; d < 1024; d <<= 1) {
        int v = ts[t];
        int add = (t >= d) ? ts[t - d] : 0;
        __syncthreads();
        ts[t] = v + add;
        __syncthreads();
    }
    int prev = (t == 0) ? 0 : ts[t - 1];
#pragma unroll
    for (int i = 0; i < 12; i++) {
        int o = prev + loc[i];
        g_off[base + i] = o;
        g_cur[base + i] = o;
    }
    if (t == 1023) g_off[N_NODES] = ts[1023];
}

__global__ void k_fill(const int* __restrict__ ei, int E) {
    int e = blockIdx.x * blockDim.x + threadIdx.x;
    if (e < E) {
        int dst = ei[E + e];
        int p = atomicAdd(&g_cur[dst], 1);
        g_csr[p] = ei[e];
    }
}

// ---------------- edge aggregation ----------------
// out[n] = relu(sum_{e: dst=n} m[src_e] + b). If outh != nullptr, the result
// is written as fp16 (half2) instead of fp32.
__global__ void k_agg(const float* __restrict__ m, const float* __restrict__ bias,
                      float* __restrict__ out, __half* __restrict__ outh, int relu) {
    int w = (blockIdx.x * blockDim.x + threadIdx.x) >> 5;
    if (w >= N_NODES) return;
    int lane = threadIdx.x & 31;
    int e = g_off[w], e1 = g_off[w + 1];
    float ax = 0.f, ay = 0.f;
    for (; e + 1 < e1; e += 2) {
        int sa = g_csr[e], sb = g_csr[e + 1];
        float2 va = *(const float2*)(m + sa * 64 + 2 * lane);
        float2 vb = *(const float2*)(m + sb * 64 + 2 * lane);
        ax += va.x; ay += va.y;
        ax += vb.x; ay += vb.y;
    }
    if (e < e1) {
        float2 va = *(const float2*)(m + g_csr[e] * 64 + 2 * lane);
        ax += va.x; ay += va.y;
    }
    if (bias) { ax += bias[2 * lane]; ay += bias[2 * lane + 1]; }
    if (relu) { ax = fmaxf(ax, 0.f); ay = fmaxf(ay, 0.f); }
    if (outh) {
        ((__half2*)outh)[w * 32 + lane] = __floats2half2_rn(ax, ay);
    } else {
        float2 r; r.x = ax; r.y = ay;
        *(float2*)(out + w * 64 + 2 * lane) = r;
    }
}

// ---------------- GEMM: Y[N,P] = X[N,K] @ W[K,P] (+bias, relu) ----------------
__global__ void __launch_bounds__(256)
k_gemm64(const float* __restrict__ X, const float* __restrict__ W,
         const float* __restrict__ bias, float* __restrict__ Y,
         int K, int P, int relu) {
    __shared__ __align__(16) float As[32 * 65];
    __shared__ __align__(16) float Bs[32 * 66];
    int tid = threadIdx.x;
    int tx = tid & 15, ty = tid >> 4;
    int rbase = blockIdx.x * 64, cbase = blockIdx.y * 64;

    ull acc[4][2];
#pragma unroll
    for (int i = 0; i < 4; i++)
#pragma unroll
        for (int j = 0; j < 2; j++) acc[i][j] = pack2(0.f, 0.f);

    for (int kc = 0; kc < K; kc += 32) {
        __syncthreads();
#pragma unroll
        for (int i = 0; i < 8; i++) {
            int idx = tid + i * 256;
            int k = idx & 31, row = idx >> 5;
            As[k * 65 + row] = X[(size_t)(rbase + row) * K + kc + k];
        }
#pragma unroll
        for (int i = 0; i < 8; i++) {
            int idx = tid + i * 256;
            int k = idx >> 6, c = idx & 63;
            Bs[k * 66 + c] = W[(size_t)(kc + k) * P + cbase + c];
        }
        __syncthreads();
#pragma unroll 8
        for (int k = 0; k < 32; k++) {
            float a[4]; ull a2[4]; ull b2[2];
#pragma unroll
            for (int i = 0; i < 4; i++) a[i] = As[k * 65 + ty + i * 16];
#pragma unroll
            for (int j = 0; j < 2; j++)
                b2[j] = *(const ull*)(&Bs[k * 66 + 2 * tx + 32 * j]);
#pragma unroll
            for (int i = 0; i < 4; i++) a2[i] = pack2(a[i], a[i]);
#pragma unroll
            for (int i = 0; i < 4; i++)
#pragma unroll
                for (int j = 0; j < 2; j++) ffma2(acc[i][j], a2[i], b2[j]);
        }
    }

#pragma unroll
    for (int i = 0; i < 4; i++) {
        int r = rbase + ty + i * 16;
#pragma unroll
        for (int j = 0; j < 2; j++) {
            int c = cbase + 2 * tx + 32 * j;
            float2 v = unpack2(acc[i][j]);
            if (bias) { v.x += bias[c]; v.y += bias[c + 1]; }
            if (relu) { v.x = fmaxf(v.x, 0.f); v.y = fmaxf(v.y, 0.f); }
            *(float2*)(&Y[(size_t)r * P + c]) = v;
        }
    }
}

// ---------------- C = S @ S^T via single-pass fp16 HMMA ----------------
// (unchanged from R11 WIN kernel)
#define TS       72          // operand row stride in halves (144B)
#define STG_ROW  68          // row-stage stride (floats)
#define STG_COL  132         // col-stage stride (floats)
#define SM_B_OFF    18432
#define SM_COL_OFF  34816    // row-stage = [0,34816), col-stage = [34816,68608)
#define SM_SST_TOTAL 68608

__global__ void __launch_bounds__(512)
k_sst_mma(const __half* __restrict__ S, float* __restrict__ C) {
    int bx = blockIdx.x, by = blockIdx.y;
    if (by > bx) return;
    bool diag = (bx == by);

    extern __shared__ __align__(16) char smem[];
    __half* Ah = (__half*)smem;
    __half* Bh = (__half*)(smem + SM_B_OFF);
    float* srow = (float*)smem;                    // [128][STG_ROW]
    float* scol = (float*)(smem + SM_COL_OFF);     // [64][STG_COL]

    int tid = threadIdx.x;
    int wid = tid >> 5;
    int lane = tid & 31;
    const size_t NN = (size_t)N_NODES;

    // operand copy: 128 rows x 64 halves (8 int4 segs/row) = 1024 int4s.
#pragma unroll
    for (int i = 0; i < 2; i++) {
        int idx = tid + i * 512;                   // 0..1023
        int row = idx >> 3, seg = idx & 7;
        const int4* sa = (const int4*)(S + (size_t)(by * 128 + row) * 64) + seg;
        *(int4*)(Ah + row * TS + seg * 8) = *sa;
        if (!diag) {
            const int4* sb = (const int4*)(S + (size_t)(bx * 128 + row) * 64) + seg;
            *(int4*)(Bh + row * TS + seg * 8) = *sb;
        }
    }
    __syncthreads();

    uint32_t aB = smem_u32(Ah);
    uint32_t bB = diag ? aB : smem_u32(Bh);
    int r0 = (wid >> 1) * 16;                      // warp's 16-row group
    int n0 = (wid & 1) * 64;                       // warp's col half

    int lr = lane & 7, ls = lane >> 3;
    uint32_t a_off = (uint32_t)((((ls & 1) * 8 + lr) * TS + (ls >> 1) * 8) * 2);
    uint32_t b_off = (uint32_t)(((lr + (ls >> 1) * 8) * TS + (ls & 1) * 8) * 2);

    float acc[8][4];
#pragma unroll
    for (int nt = 0; nt < 8; nt++)
#pragma unroll
        for (int q = 0; q < 4; q++) acc[nt][q] = 0.f;

#pragma unroll
    for (int ks = 0; ks < 4; ks++) {
        uint32_t koff = (uint32_t)(ks * 32);
        uint32_t a0, a1, a2, a3;
        ldsm_x4(a0, a1, a2, a3, aB + (uint32_t)(r0 * TS * 2) + koff + a_off);
#pragma unroll
        for (int np = 0; np < 4; np++) {
            uint32_t b0, b1, b2, b3;
            ldsm_x4(b0, b1, b2, b3,
                    bB + (uint32_t)((n0 + np * 16) * TS * 2) + koff + b_off);
            mma_f16(acc[2 * np],     a0, a1, a2, a3, b0, b1);
            mma_f16(acc[2 * np + 1], a0, a1, a2, a3, b2, b3);
        }
    }
    __syncthreads();                               // operands dead

    int gid = lane >> 2, tig = lane & 3;
    int rbase = by * 128, cbase = bx * 128;

#pragma unroll 1
    for (int h = 0; h < 2; h++) {
        if ((wid & 1) == h) {
            int rl = r0 + gid;
#pragma unroll
            for (int nt = 0; nt < 8; nt++) {
                int cl = 8 * nt + 2 * tig;
                float2 v0; v0.x = acc[nt][0]; v0.y = acc[nt][1];
                float2 v1; v1.x = acc[nt][2]; v1.y = acc[nt][3];
                *(float2*)&srow[rl * STG_ROW + cl] = v0;
                *(float2*)&srow[(rl + 8) * STG_ROW + cl] = v1;
                if (!diag) {
                    scol[cl * STG_COL + rl]            = acc[nt][0];
                    scol[(cl + 1) * STG_COL + rl]      = acc[nt][1];
                    scol[cl * STG_COL + rl + 8]        = acc[nt][2];
                    scol[(cl + 1) * STG_COL + rl + 8]  = acc[nt][3];
                }
            }
        }
        __syncthreads();
#pragma unroll
        for (int i = 0; i < 4; i++) {
            int lin = tid + i * 512;
            int row = lin >> 4, c4 = (lin & 15) * 4;
            float4 v = *(float4*)&srow[row * STG_ROW + c4];
            stcs4(&C[(size_t)(rbase + row) * NN + cbase + h * 64 + c4], v);
        }
        if (!diag) {
#pragma unroll
            for (int i = 0; i < 4; i++) {
                int lin = tid + i * 512;
                int c = lin >> 5, q = (lin & 31) * 4;
                float4 v = *(float4*)&scol[c * STG_COL + q];
                stcs4(&C[(size_t)(cbase + h * 64 + c) * NN + rbase + q], v);
            }
        }
        __syncthreads();
    }
}

// ---------------- launch ----------------
static float* symf(const void* sym) {
    void* p = nullptr;
    cudaGetSymbolAddress(&p, sym);
    return (float*)p;
}

extern "C" void kernel_launch(void* const* d_in, const int* in_sizes, int n_in,
                              void* d_out, int out_size) {
    const float* h   = (const float*)d_in[0];
    const int*   ei  = (const int*)d_in[1];
    const float* W1  = (const float*)d_in[2];
    const float* b1  = (const float*)d_in[3];
    const float* W2  = (const float*)d_in[4];
    const float* b2  = (const float*)d_in[5];
    const float* Wa1 = (const float*)d_in[6];
    const float* ba1 = (const float*)d_in[7];
    const float* Wa2 = (const float*)d_in[8];
    const float* ba2 = (const float*)d_in[9];
    const float* Ws  = (const float*)d_in[10];
    const float* bs  = (const float*)d_in[11];
    float* out = (float*)d_out;
    int E = in_sizes[1] / 2;

    float*  m     = symf(g_m);
    float*  m2    = symf(g_m2);
    float*  x     = symf(g_x);
    float*  x2    = symf(g_x2);
    float*  xa    = symf(g_xa);
    float*  aggxa = symf(g_aggxa);
    __half* sh    = (__half*)symf(g_sh);

    float* out_xhat = out + (size_t)N_NODES * (size_t)N_NODES;

    int eb = (E + 255) / 256;

    static cudaStream_t s2 = nullptr;
    static cudaEvent_t ev_fork = nullptr, ev_g512 = nullptr,
                       ev_sh = nullptr, ev_sst = nullptr;
    if (!s2) {
        cudaFuncSetAttribute(k_sst_mma, cudaFuncAttributeMaxDynamicSharedMemorySize,
                             SM_SST_TOTAL);
        cudaStreamCreateWithFlags(&s2, cudaStreamNonBlocking);
        cudaEventCreateWithFlags(&ev_fork, cudaEventDisableTiming);
        cudaEventCreateWithFlags(&ev_g512, cudaEventDisableTiming);
        cudaEventCreateWithFlags(&ev_sh, cudaEventDisableTiming);
        cudaEventCreateWithFlags(&ev_sst, cudaEventDisableTiming);
    }

    // ---- fork: h@W1 on side stream, CSR build on main stream (independent) ----
    cudaEventRecord(ev_fork, 0);
    cudaStreamWaitEvent(s2, ev_fork, 0);
    k_gemm64<<<dim3(192, 1), 256, 0, s2>>>(h, W1, nullptr, m, 512, 64, 0);
    cudaEventRecord(ev_g512, s2);

    k_zero_deg<<<(N_NODES + 255) / 256, 256>>>();
    k_count<<<eb, 256>>>(ei, E);
    k_scan<<<1, 1024>>>();
    k_fill<<<eb, 256>>>(ei, E);

    cudaStreamWaitEvent(0, ev_g512, 0);

    // encoder layer 1: x = relu(agg(h @ W1) + b1)
    k_agg<<<1536, 256>>>(m, b1, x, nullptr, 1);
    // encoder layer 2: x2 = relu(agg(x @ W2) + b2)
    k_gemm64<<<dim3(192, 1), 256>>>(x, W2, nullptr, m, 64, 64, 0);
    k_agg<<<1536, 256>>>(m, b2, x2, nullptr, 1);
    // structure decoder: s = relu(agg(x2 @ Ws) + bs) in fp16
    k_gemm64<<<dim3(192, 1), 256>>>(x2, Ws, nullptr, m, 64, 64, 0);
    k_agg<<<1536, 256>>>(m, bs, nullptr, sh, 1);

    // ---- fork: C = s s^T on side stream; attr decoder on main (disjoint data) ----
    cudaEventRecord(ev_sh, 0);
    cudaStreamWaitEvent(s2, ev_sh, 0);
    k_sst_mma<<<dim3(NTILE, NTILE), 512, SM_SST_TOTAL, s2>>>(sh, out);
    cudaEventRecord(ev_sst, s2);

    // attribute decoder (uses m2 scratch -> no conflict with sst/struct chain)
    k_gemm64<<<dim3(192, 1), 256>>>(x2, Wa1, nullptr, m2, 64, 64, 0);
    k_agg<<<1536, 256>>>(m2, ba1, xa, nullptr, 1);
    k_agg<<<1536, 256>>>(xa, nullptr, aggxa, nullptr, 0);
    k_gemm64<<<dim3(192, 8), 256>>>(aggxa, Wa2, ba2, out_xhat, 64, 512, 1);

    // join
    cudaStreamWaitEvent(0, ev_sst, 0);
}

// round 14
// speedup vs baseline: 1.5768x; 1.1192x over previous
#include <cuda_runtime.h>
#include <cuda_fp16.h>
#include <cstdint>

// Problem constants (fixed by the dataset)
#define N_NODES 12288
#define F_DIMV  512
#define H_DIMV  64
#define E_MAX   393216
#define NTILE   96          // 12288 / 128

typedef unsigned long long ull;

// ---------------- f32x2 packed helpers ----------------
__device__ __forceinline__ void ffma2(ull& d, ull a, ull b) {
    asm("fma.rn.f32x2 %0, %1, %2, %0;" : "+l"(d) : "l"(a), "l"(b));
}
__device__ __forceinline__ ull pack2(float x, float y) {
    ull r;
    asm("mov.b64 %0, {%1, %2};" : "=l"(r) : "f"(x), "f"(y));
    return r;
}
__device__ __forceinline__ float2 unpack2(ull v) {
    float2 r;
    asm("mov.b64 {%0, %1}, %2;" : "=f"(r.x), "=f"(r.y) : "l"(v));
    return r;
}

// ---------------- warp MMA helpers (sm_80+ baseline) ----------------
__device__ __forceinline__ uint32_t smem_u32(const void* p) {
    uint32_t a;
    asm("{ .reg .u64 t; cvta.to.shared.u64 t, %1; cvt.u32.u64 %0, t; }"
        : "=r"(a) : "l"(p));
    return a;
}
__device__ __forceinline__ void ldsm_x4(uint32_t& r0, uint32_t& r1, uint32_t& r2,
                                        uint32_t& r3, uint32_t addr) {
    asm volatile("ldmatrix.sync.aligned.m8n8.x4.shared.b16 {%0,%1,%2,%3}, [%4];"
                 : "=r"(r0), "=r"(r1), "=r"(r2), "=r"(r3) : "r"(addr));
}
__device__ __forceinline__ void mma_f16(float d[4], uint32_t a0, uint32_t a1,
                                        uint32_t a2, uint32_t a3,
                                        uint32_t b0, uint32_t b1) {
    asm volatile(
        "mma.sync.aligned.m16n8k16.row.col.f32.f16.f16.f32 "
        "{%0,%1,%2,%3}, {%4,%5,%6,%7}, {%8,%9}, {%0,%1,%2,%3};"
        : "+f"(d[0]), "+f"(d[1]), "+f"(d[2]), "+f"(d[3])
        : "r"(a0), "r"(a1), "r"(a2), "r"(a3), "r"(b0), "r"(b1));
}
__device__ __forceinline__ void stcs4(float* p, float4 v) {
    asm volatile("st.global.cs.v4.f32 [%0], {%1,%2,%3,%4};"
                 :: "l"(p), "f"(v.x), "f"(v.y), "f"(v.z), "f"(v.w) : "memory");
}

// ---------------- scratch (no allocations allowed) ----------------
__device__ float  g_m[N_NODES * H_DIMV];
__device__ float  g_x[N_NODES * H_DIMV];
__device__ float  g_x2[N_NODES * H_DIMV];
__device__ float  g_xa[N_NODES * H_DIMV];
__device__ float  g_aggxa[N_NODES * H_DIMV];
__device__ __half g_sh[N_NODES * H_DIMV];      // structure embedding (fp16)
__device__ int    g_deg[N_NODES];
__device__ int    g_off[N_NODES + 1];
__device__ int    g_cur[N_NODES];
__device__ int    g_csr[E_MAX];

// ---------------- CSR build ----------------
__global__ void k_zero_deg() {
    int i = blockIdx.x * blockDim.x + threadIdx.x;
    if (i < N_NODES) g_deg[i] = 0;
}

__global__ void k_count(const int* __restrict__ ei, int E) {
    int e = blockIdx.x * blockDim.x + threadIdx.x;
    if (e < E) atomicAdd(&g_deg[ei[E + e]], 1);
}

// warp-shuffle scan: 1024 threads x 12 items, 2 barriers total
__global__ void k_scan() {
    __shared__ int wsum[32];
    int t = threadIdx.x;
    int lane = t & 31, w = t >> 5;
    int base = t * 12;
    int loc[12];
    int s = 0;
#pragma unroll
    for (int i = 0; i < 12; i++) { loc[i] = s; s += g_deg[base + i]; }
    int v = s;
#pragma unroll
    for (int d = 1; d < 32; d <<= 1) {
        int u = __shfl_up_sync(0xFFFFFFFFu, v, d);
        if (lane >= d) v += u;
    }
    if (lane == 31) wsum[w] = v;
    __syncthreads();
    if (w == 0) {
        int x = wsum[lane];
#pragma unroll
        for (int d = 1; d < 32; d <<= 1) {
            int u = __shfl_up_sync(0xFFFFFFFFu, x, d);
            if (lane >= d) x += u;
        }
        wsum[lane] = x;
    }
    __syncthreads();
    int prev = v - s + (w ? wsum[w - 1] : 0);
#pragma unroll
    for (int i = 0; i < 12; i++) {
        int o = prev + loc[i];
        g_off[base + i] = o;
        g_cur[base + i] = o;
    }
    if (t == 1023) g_off[N_NODES] = wsum[31];
}

__global__ void k_fill(const int* __restrict__ ei, int E) {
    int e = blockIdx.x * blockDim.x + threadIdx.x;
    if (e < E) {
        int dst = ei[E + e];
        int p = atomicAdd(&g_cur[dst], 1);
        g_csr[p] = ei[e];
    }
}

// ---------------- edge aggregation ----------------
__global__ void k_agg(const float* __restrict__ m, const float* __restrict__ bias,
                      float* __restrict__ out, __half* __restrict__ outh, int relu) {
    int w = (blockIdx.x * blockDim.x + threadIdx.x) >> 5;
    if (w >= N_NODES) return;
    int lane = threadIdx.x & 31;
    int e = g_off[w], e1 = g_off[w + 1];
    float ax = 0.f, ay = 0.f;
    for (; e + 1 < e1; e += 2) {
        int sa = g_csr[e], sb = g_csr[e + 1];
        float2 va = *(const float2*)(m + sa * 64 + 2 * lane);
        float2 vb = *(const float2*)(m + sb * 64 + 2 * lane);
        ax += va.x; ay += va.y;
        ax += vb.x; ay += vb.y;
    }
    if (e < e1) {
        float2 va = *(const float2*)(m + g_csr[e] * 64 + 2 * lane);
        ax += va.x; ay += va.y;
    }
    if (bias) { ax += bias[2 * lane]; ay += bias[2 * lane + 1]; }
    if (relu) { ax = fmaxf(ax, 0.f); ay = fmaxf(ay, 0.f); }
    if (outh) {
        ((__half2*)outh)[w * 32 + lane] = __floats2half2_rn(ax, ay);
    } else {
        float2 r; r.x = ax; r.y = ay;
        *(float2*)(out + w * 64 + 2 * lane) = r;
    }
}

// ---------------- GEMM: Y[N,P] = X[N,K] @ W[K,P] (+bias, relu) ----------------
// If Yh != nullptr, result is written fp16 (row-major [N,P]) instead of Y.
__global__ void __launch_bounds__(256)
k_gemm64(const float* __restrict__ X, const float* __restrict__ W,
         const float* __restrict__ bias, float* __restrict__ Y,
         __half* __restrict__ Yh, int K, int P, int relu) {
    __shared__ __align__(16) float As[32 * 65];
    __shared__ __align__(16) float Bs[32 * 66];
    int tid = threadIdx.x;
    int tx = tid & 15, ty = tid >> 4;
    int rbase = blockIdx.x * 64, cbase = blockIdx.y * 64;

    ull acc[4][2];
#pragma unroll
    for (int i = 0; i < 4; i++)
#pragma unroll
        for (int j = 0; j < 2; j++) acc[i][j] = pack2(0.f, 0.f);

    for (int kc = 0; kc < K; kc += 32) {
        __syncthreads();
#pragma unroll
        for (int i = 0; i < 8; i++) {
            int idx = tid + i * 256;
            int k = idx & 31, row = idx >> 5;
            As[k * 65 + row] = X[(size_t)(rbase + row) * K + kc + k];
        }
#pragma unroll
        for (int i = 0; i < 8; i++) {
            int idx = tid + i * 256;
            int k = idx >> 6, c = idx & 63;
            Bs[k * 66 + c] = W[(size_t)(kc + k) * P + cbase + c];
        }
        __syncthreads();
#pragma unroll 8
        for (int k = 0; k < 32; k++) {
            float a[4]; ull a2[4]; ull b2[2];
#pragma unroll
            for (int i = 0; i < 4; i++) a[i] = As[k * 65 + ty + i * 16];
#pragma unroll
            for (int j = 0; j < 2; j++)
                b2[j] = *(const ull*)(&Bs[k * 66 + 2 * tx + 32 * j]);
#pragma unroll
            for (int i = 0; i < 4; i++) a2[i] = pack2(a[i], a[i]);
#pragma unroll
            for (int i = 0; i < 4; i++)
#pragma unroll
                for (int j = 0; j < 2; j++) ffma2(acc[i][j], a2[i], b2[j]);
        }
    }

#pragma unroll
    for (int i = 0; i < 4; i++) {
        int r = rbase + ty + i * 16;
#pragma unroll
        for (int j = 0; j < 2; j++) {
            int c = cbase + 2 * tx + 32 * j;
            float2 v = unpack2(acc[i][j]);
            if (bias) { v.x += bias[c]; v.y += bias[c + 1]; }
            if (relu) { v.x = fmaxf(v.x, 0.f); v.y = fmaxf(v.y, 0.f); }
            if (Yh) {
                *(__half2*)(&Yh[(size_t)r * P + c]) = __floats2half2_rn(v.x, v.y);
            } else {
                *(float2*)(&Y[(size_t)r * P + c]) = v;
            }
        }
    }
}

// ---------------- C = S @ S^T via single-pass fp16 HMMA ----------------
// (unchanged from R11/R13 WIN kernel)
#define TS       72          // operand row stride in halves (144B)
#define STG_ROW  68          // row-stage stride (floats)
#define STG_COL  132         // col-stage stride (floats)
#define SM_B_OFF    18432
#define SM_COL_OFF  34816
#define SM_SST_TOTAL 68608

__global__ void __launch_bounds__(512)
k_sst_mma(const __half* __restrict__ S, float* __restrict__ C) {
    int bx = blockIdx.x, by = blockIdx.y;
    if (by > bx) return;
    bool diag = (bx == by);

    extern __shared__ __align__(16) char smem[];
    __half* Ah = (__half*)smem;
    __half* Bh = (__half*)(smem + SM_B_OFF);
    float* srow = (float*)smem;                    // [128][STG_ROW]
    float* scol = (float*)(smem + SM_COL_OFF);     // [64][STG_COL]

    int tid = threadIdx.x;
    int wid = tid >> 5;
    int lane = tid & 31;
    const size_t NN = (size_t)N_NODES;

#pragma unroll
    for (int i = 0; i < 2; i++) {
        int idx = tid + i * 512;                   // 0..1023
        int row = idx >> 3, seg = idx & 7;
        const int4* sa = (const int4*)(S + (size_t)(by * 128 + row) * 64) + seg;
        *(int4*)(Ah + row * TS + seg * 8) = *sa;
        if (!diag) {
            const int4* sb = (const int4*)(S + (size_t)(bx * 128 + row) * 64) + seg;
            *(int4*)(Bh + row * TS + seg * 8) = *sb;
        }
    }
    __syncthreads();

    uint32_t aB = smem_u32(Ah);
    uint32_t bB = diag ? aB : smem_u32(Bh);
    int r0 = (wid >> 1) * 16;
    int n0 = (wid & 1) * 64;

    int lr = lane & 7, ls = lane >> 3;
    uint32_t a_off = (uint32_t)((((ls & 1) * 8 + lr) * TS + (ls >> 1) * 8) * 2);
    uint32_t b_off = (uint32_t)(((lr + (ls >> 1) * 8) * TS + (ls & 1) * 8) * 2);

    float acc[8][4];
#pragma unroll
    for (int nt = 0; nt < 8; nt++)
#pragma unroll
        for (int q = 0; q < 4; q++) acc[nt][q] = 0.f;

#pragma unroll
    for (int ks = 0; ks < 4; ks++) {
        uint32_t koff = (uint32_t)(ks * 32);
        uint32_t a0, a1, a2, a3;
        ldsm_x4(a0, a1, a2, a3, aB + (uint32_t)(r0 * TS * 2) + koff + a_off);
#pragma unroll
        for (int np = 0; np < 4; np++) {
            uint32_t b0, b1, b2, b3;
            ldsm_x4(b0, b1, b2, b3,
                    bB + (uint32_t)((n0 + np * 16) * TS * 2) + koff + b_off);
            mma_f16(acc[2 * np],     a0, a1, a2, a3, b0, b1);
            mma_f16(acc[2 * np + 1], a0, a1, a2, a3, b2, b3);
        }
    }
    __syncthreads();

    int gid = lane >> 2, tig = lane & 3;
    int rbase = by * 128, cbase = bx * 128;

#pragma unroll 1
    for (int h = 0; h < 2; h++) {
        if ((wid & 1) == h) {
            int rl = r0 + gid;
#pragma unroll
            for (int nt = 0; nt < 8; nt++) {
                int cl = 8 * nt + 2 * tig;
                float2 v0; v0.x = acc[nt][0]; v0.y = acc[nt][1];
                float2 v1; v1.x = acc[nt][2]; v1.y = acc[nt][3];
                *(float2*)&srow[rl * STG_ROW + cl] = v0;
                *(float2*)&srow[(rl + 8) * STG_ROW + cl] = v1;
                if (!diag) {
                    scol[cl * STG_COL + rl]            = acc[nt][0];
                    scol[(cl + 1) * STG_COL + rl]      = acc[nt][1];
                    scol[cl * STG_COL + rl + 8]        = acc[nt][2];
                    scol[(cl + 1) * STG_COL + rl + 8]  = acc[nt][3];
                }
            }
        }
        __syncthreads();
#pragma unroll
        for (int i = 0; i < 4; i++) {
            int lin = tid + i * 512;
            int row = lin >> 4, c4 = (lin & 15) * 4;
            float4 v = *(float4*)&srow[row * STG_ROW + c4];
            stcs4(&C[(size_t)(rbase + row) * NN + cbase + h * 64 + c4], v);
        }
        if (!diag) {
#pragma unroll
            for (int i = 0; i < 4; i++) {
                int lin = tid + i * 512;
                int c = lin >> 5, q = (lin & 31) * 4;
                float4 v = *(float4*)&scol[c * STG_COL + q];
                stcs4(&C[(size_t)(cbase + h * 64 + c) * NN + rbase + q], v);
            }
        }
        __syncthreads();
    }
}

// ---------------- launch ----------------
static float* symf(const void* sym) {
    void* p = nullptr;
    cudaGetSymbolAddress(&p, sym);
    return (float*)p;
}

extern "C" void kernel_launch(void* const* d_in, const int* in_sizes, int n_in,
                              void* d_out, int out_size) {
    const float* h   = (const float*)d_in[0];
    const int*   ei  = (const int*)d_in[1];
    const float* W1  = (const float*)d_in[2];
    const float* b1  = (const float*)d_in[3];
    const float* W2  = (const float*)d_in[4];
    const float* b2  = (const float*)d_in[5];
    const float* Wa1 = (const float*)d_in[6];
    const float* ba1 = (const float*)d_in[7];
    const float* Wa2 = (const float*)d_in[8];
    const float* ba2 = (const float*)d_in[9];
    const float* Ws  = (const float*)d_in[10];
    const float* bs  = (const float*)d_in[11];
    float* out = (float*)d_out;
    int E = in_sizes[1] / 2;

    float*  m     = symf(g_m);
    float*  x     = symf(g_x);
    float*  x2    = symf(g_x2);
    float*  xa    = symf(g_xa);
    float*  aggxa = symf(g_aggxa);
    __half* sh    = (__half*)symf(g_sh);

    float* out_xhat = out + (size_t)N_NODES * (size_t)N_NODES;

    int eb = (E + 255) / 256;

    static cudaStream_t s2 = nullptr;
    static cudaEvent_t ev_fork = nullptr, ev_g512 = nullptr,
                       ev_a2 = nullptr, ev_sst = nullptr;
    if (!s2) {
        cudaFuncSetAttribute(k_sst_mma, cudaFuncAttributeMaxDynamicSharedMemorySize,
                             SM_SST_TOTAL);
        cudaStreamCreateWithFlags(&s2, cudaStreamNonBlocking);
        cudaEventCreateWithFlags(&ev_fork, cudaEventDisableTiming);
        cudaEventCreateWithFlags(&ev_g512, cudaEventDisableTiming);
        cudaEventCreateWithFlags(&ev_a2, cudaEventDisableTiming);
        cudaEventCreateWithFlags(&ev_sst, cudaEventDisableTiming);
    }

    // ---- fork: h@W1 on side stream, CSR build on main stream (independent) ----
    cudaEventRecord(ev_fork, 0);
    cudaStreamWaitEvent(s2, ev_fork, 0);
    k_gemm64<<<dim3(192, 1), 256, 0, s2>>>(h, W1, nullptr, m, nullptr, 512, 64, 0);
    cudaEventRecord(ev_g512, s2);

    k_zero_deg<<<(N_NODES + 255) / 256, 256>>>();
    k_count<<<eb, 256>>>(ei, E);
    k_scan<<<1, 1024>>>();
    k_fill<<<eb, 256>>>(ei, E);

    cudaStreamWaitEvent(0, ev_g512, 0);

    // encoder layer 1: x = relu(agg(h@W1) + b1)
    k_agg<<<1536, 256>>>(m, b1, x, nullptr, 1);
    // encoder layer 2 (agg-then-gemm): x2 = relu(agg(x)@W2 + b2)
    k_agg<<<1536, 256>>>(x, nullptr, m, nullptr, 0);               // A_x -> m
    k_gemm64<<<dim3(192, 1), 256>>>(m, W2, b2, x2, nullptr, 64, 64, 1);
    // shared aggregation for both decoders: A2 = agg(x2) -> m
    k_agg<<<1536, 256>>>(x2, nullptr, m, nullptr, 0);
    cudaEventRecord(ev_a2, 0);

    // ---- side stream: s = relu(A2@Ws + bs) (fp16), then C = s s^T ----
    cudaStreamWaitEvent(s2, ev_a2, 0);
    k_gemm64<<<dim3(192, 1), 256, 0, s2>>>(m, Ws, bs, nullptr, sh, 64, 64, 1);
    k_sst_mma<<<dim3(NTILE, NTILE), 512, SM_SST_TOTAL, s2>>>(sh, out);
    cudaEventRecord(ev_sst, s2);

    // ---- main stream: attribute decoder ----
    k_gemm64<<<dim3(192, 1), 256>>>(m, Wa1, ba1, xa, nullptr, 64, 64, 1);
    k_agg<<<1536, 256>>>(xa, nullptr, aggxa, nullptr, 0);
    k_gemm64<<<dim3(192, 8), 256>>>(aggxa, Wa2, ba2, out_xhat, nullptr, 64, 512, 1);

    // join
    cudaStreamWaitEvent(0, ev_sst, 0);
}

// round 15
// speedup vs baseline: 1.6086x; 1.0201x over previous
#include <cuda_runtime.h>
#include <cuda_fp16.h>
#include <cstdint>

// Problem constants (fixed by the dataset)
#define N_NODES 12288
#define F_DIMV  512
#define H_DIMV  64
#define E_MAX   393216
#define NTILE   96          // 12288 / 128

typedef unsigned long long ull;

// ---------------- f32x2 packed helpers ----------------
__device__ __forceinline__ void ffma2(ull& d, ull a, ull b) {
    asm("fma.rn.f32x2 %0, %1, %2, %0;" : "+l"(d) : "l"(a), "l"(b));
}
__device__ __forceinline__ ull pack2(float x, float y) {
    ull r;
    asm("mov.b64 %0, {%1, %2};" : "=l"(r) : "f"(x), "f"(y));
    return r;
}
__device__ __forceinline__ float2 unpack2(ull v) {
    float2 r;
    asm("mov.b64 {%0, %1}, %2;" : "=f"(r.x), "=f"(r.y) : "l"(v));
    return r;
}

// ---------------- warp MMA helpers (sm_80+ baseline) ----------------
__device__ __forceinline__ uint32_t smem_u32(const void* p) {
    uint32_t a;
    asm("{ .reg .u64 t; cvta.to.shared.u64 t, %1; cvt.u32.u64 %0, t; }"
        : "=r"(a) : "l"(p));
    return a;
}
__device__ __forceinline__ void ldsm_x4(uint32_t& r0, uint32_t& r1, uint32_t& r2,
                                        uint32_t& r3, uint32_t addr) {
    asm volatile("ldmatrix.sync.aligned.m8n8.x4.shared.b16 {%0,%1,%2,%3}, [%4];"
                 : "=r"(r0), "=r"(r1), "=r"(r2), "=r"(r3) : "r"(addr));
}
__device__ __forceinline__ void mma_f16(float d[4], uint32_t a0, uint32_t a1,
                                        uint32_t a2, uint32_t a3,
                                        uint32_t b0, uint32_t b1) {
    asm volatile(
        "mma.sync.aligned.m16n8k16.row.col.f32.f16.f16.f32 "
        "{%0,%1,%2,%3}, {%4,%5,%6,%7}, {%8,%9}, {%0,%1,%2,%3};"
        : "+f"(d[0]), "+f"(d[1]), "+f"(d[2]), "+f"(d[3])
        : "r"(a0), "r"(a1), "r"(a2), "r"(a3), "r"(b0), "r"(b1));
}
__device__ __forceinline__ void stcs4(float* p, float4 v) {
    asm volatile("st.global.cs.v4.f32 [%0], {%1,%2,%3,%4};"
                 :: "l"(p), "f"(v.x), "f"(v.y), "f"(v.z), "f"(v.w) : "memory");
}

// ---------------- scratch (no allocations allowed) ----------------
__device__ float  g_m[N_NODES * H_DIMV];
__device__ float  g_x[N_NODES * H_DIMV];
__device__ float  g_x2[N_NODES * H_DIMV];
__device__ float  g_xa[N_NODES * H_DIMV];
__device__ float  g_aggxa[N_NODES * H_DIMV];
__device__ __half g_sh[N_NODES * H_DIMV];      // structure embedding (fp16)
__device__ int    g_deg[N_NODES];
__device__ int    g_off[N_NODES + 1];
__device__ int    g_cur[N_NODES];
__device__ int    g_csr[E_MAX];

// ---------------- CSR build ----------------
__global__ void k_zero_deg() {
    int i = blockIdx.x * blockDim.x + threadIdx.x;
    if (i < N_NODES) g_deg[i] = 0;
}

__global__ void k_count(const int* __restrict__ ei, int E) {
    int e = blockIdx.x * blockDim.x + threadIdx.x;
    if (e < E) atomicAdd(&g_deg[ei[E + e]], 1);
}

// warp-shuffle scan: 1024 threads x 12 items (int4-vectorized), 2 barriers
__global__ void k_scan() {
    __shared__ int wsum[32];
    int t = threadIdx.x;
    int lane = t & 31, w = t >> 5;
    int base = t * 12;
    int d4[12];
#pragma unroll
    for (int i = 0; i < 3; i++) {
        int4 v4 = *(const int4*)(&g_deg[base + 4 * i]);
        d4[4 * i] = v4.x; d4[4 * i + 1] = v4.y;
        d4[4 * i + 2] = v4.z; d4[4 * i + 3] = v4.w;
    }
    int loc[12];
    int s = 0;
#pragma unroll
    for (int i = 0; i < 12; i++) { loc[i] = s; s += d4[i]; }
    int v = s;
#pragma unroll
    for (int d = 1; d < 32; d <<= 1) {
        int u = __shfl_up_sync(0xFFFFFFFFu, v, d);
        if (lane >= d) v += u;
    }
    if (lane == 31) wsum[w] = v;
    __syncthreads();
    if (w == 0) {
        int x = wsum[lane];
#pragma unroll
        for (int d = 1; d < 32; d <<= 1) {
            int u = __shfl_up_sync(0xFFFFFFFFu, x, d);
            if (lane >= d) x += u;
        }
        wsum[lane] = x;
    }
    __syncthreads();
    int prev = v - s + (w ? wsum[w - 1] : 0);
#pragma unroll
    for (int i = 0; i < 3; i++) {
        int4 o4;
        o4.x = prev + loc[4 * i];
        o4.y = prev + loc[4 * i + 1];
        o4.z = prev + loc[4 * i + 2];
        o4.w = prev + loc[4 * i + 3];
        *(int4*)(&g_off[base + 4 * i]) = o4;
        *(int4*)(&g_cur[base + 4 * i]) = o4;
    }
    if (t == 1023) g_off[N_NODES] = wsum[31];
}

__global__ void k_fill(const int* __restrict__ ei, int E) {
    int e = blockIdx.x * blockDim.x + threadIdx.x;
    if (e < E) {
        int dst = ei[E + e];
        int p = atomicAdd(&g_cur[dst], 1);
        g_csr[p] = ei[e];
    }
}

// ---------------- edge aggregation ----------------
__global__ void k_agg(const float* __restrict__ m, const float* __restrict__ bias,
                      float* __restrict__ out, __half* __restrict__ outh, int relu) {
    int w = (blockIdx.x * blockDim.x + threadIdx.x) >> 5;
    if (w >= N_NODES) return;
    int lane = threadIdx.x & 31;
    int e = g_off[w], e1 = g_off[w + 1];
    float ax = 0.f, ay = 0.f;
    for (; e + 1 < e1; e += 2) {
        int sa = g_csr[e], sb = g_csr[e + 1];
        float2 va = *(const float2*)(m + sa * 64 + 2 * lane);
        float2 vb = *(const float2*)(m + sb * 64 + 2 * lane);
        ax += va.x; ay += va.y;
        ax += vb.x; ay += vb.y;
    }
    if (e < e1) {
        float2 va = *(const float2*)(m + g_csr[e] * 64 + 2 * lane);
        ax += va.x; ay += va.y;
    }
    if (bias) { ax += bias[2 * lane]; ay += bias[2 * lane + 1]; }
    if (relu) { ax = fmaxf(ax, 0.f); ay = fmaxf(ay, 0.f); }
    if (outh) {
        ((__half2*)outh)[w * 32 + lane] = __floats2half2_rn(ax, ay);
    } else {
        float2 r; r.x = ax; r.y = ay;
        *(float2*)(out + w * 64 + 2 * lane) = r;
    }
}

// ---------------- GEMM: Y[N,P] = X[N,K] @ W[K,P] (+bias, relu) ----------------
__global__ void __launch_bounds__(256)
k_gemm64(const float* __restrict__ X, const float* __restrict__ W,
         const float* __restrict__ bias, float* __restrict__ Y,
         __half* __restrict__ Yh, int K, int P, int relu) {
    __shared__ __align__(16) float As[32 * 65];
    __shared__ __align__(16) float Bs[32 * 66];
    int tid = threadIdx.x;
    int tx = tid & 15, ty = tid >> 4;
    int rbase = blockIdx.x * 64, cbase = blockIdx.y * 64;

    ull acc[4][2];
#pragma unroll
    for (int i = 0; i < 4; i++)
#pragma unroll
        for (int j = 0; j < 2; j++) acc[i][j] = pack2(0.f, 0.f);

    for (int kc = 0; kc < K; kc += 32) {
        __syncthreads();
#pragma unroll
        for (int i = 0; i < 8; i++) {
            int idx = tid + i * 256;
            int k = idx & 31, row = idx >> 5;
            As[k * 65 + row] = X[(size_t)(rbase + row) * K + kc + k];
        }
#pragma unroll
        for (int i = 0; i < 8; i++) {
            int idx = tid + i * 256;
            int k = idx >> 6, c = idx & 63;
            Bs[k * 66 + c] = W[(size_t)(kc + k) * P + cbase + c];
        }
        __syncthreads();
#pragma unroll 8
        for (int k = 0; k < 32; k++) {
            float a[4]; ull a2[4]; ull b2[2];
#pragma unroll
            for (int i = 0; i < 4; i++) a[i] = As[k * 65 + ty + i * 16];
#pragma unroll
            for (int j = 0; j < 2; j++)
                b2[j] = *(const ull*)(&Bs[k * 66 + 2 * tx + 32 * j]);
#pragma unroll
            for (int i = 0; i < 4; i++) a2[i] = pack2(a[i], a[i]);
#pragma unroll
            for (int i = 0; i < 4; i++)
#pragma unroll
                for (int j = 0; j < 2; j++) ffma2(acc[i][j], a2[i], b2[j]);
        }
    }

#pragma unroll
    for (int i = 0; i < 4; i++) {
        int r = rbase + ty + i * 16;
#pragma unroll
        for (int j = 0; j < 2; j++) {
            int c = cbase + 2 * tx + 32 * j;
            float2 v = unpack2(acc[i][j]);
            if (bias) { v.x += bias[c]; v.y += bias[c + 1]; }
            if (relu) { v.x = fmaxf(v.x, 0.f); v.y = fmaxf(v.y, 0.f); }
            if (Yh) {
                *(__half2*)(&Yh[(size_t)r * P + c]) = __floats2half2_rn(v.x, v.y);
            } else {
                *(float2*)(&Y[(size_t)r * P + c]) = v;
            }
        }
    }
}

// ---------------- C = S @ S^T via single-pass fp16 HMMA ----------------
// R14 change: __launch_bounds__(512, 3) -> 3 CTAs/SM (was reg-capped at 2).
// Store-bound kernel; extra resident warps hide the syncthreads-fenced
// store-round tails. Few spills OK.
#define TS       72          // operand row stride in halves (144B)
#define STG_ROW  68          // row-stage stride (floats)
#define STG_COL  132         // col-stage stride (floats)
#define SM_B_OFF    18432
#define SM_COL_OFF  34816
#define SM_SST_TOTAL 68608

__global__ void __launch_bounds__(512, 3)
k_sst_mma(const __half* __restrict__ S, float* __restrict__ C) {
    int bx = blockIdx.x, by = blockIdx.y;
    if (by > bx) return;
    bool diag = (bx == by);

    extern __shared__ __align__(16) char smem[];
    __half* Ah = (__half*)smem;
    __half* Bh = (__half*)(smem + SM_B_OFF);
    float* srow = (float*)smem;                    // [128][STG_ROW]
    float* scol = (float*)(smem + SM_COL_OFF);     // [64][STG_COL]

    int tid = threadIdx.x;
    int wid = tid >> 5;
    int lane = tid & 31;
    const size_t NN = (size_t)N_NODES;

#pragma unroll
    for (int i = 0; i < 2; i++) {
        int idx = tid + i * 512;                   // 0..1023
        int row = idx >> 3, seg = idx & 7;
        const int4* sa = (const int4*)(S + (size_t)(by * 128 + row) * 64) + seg;
        *(int4*)(Ah + row * TS + seg * 8) = *sa;
        if (!diag) {
            const int4* sb = (const int4*)(S + (size_t)(bx * 128 + row) * 64) + seg;
            *(int4*)(Bh + row * TS + seg * 8) = *sb;
        }
    }
    __syncthreads();

    uint32_t aB = smem_u32(Ah);
    uint32_t bB = diag ? aB : smem_u32(Bh);
    int r0 = (wid >> 1) * 16;
    int n0 = (wid & 1) * 64;

    int lr = lane & 7, ls = lane >> 3;
    uint32_t a_off = (uint32_t)((((ls & 1) * 8 + lr) * TS + (ls >> 1) * 8) * 2);
    uint32_t b_off = (uint32_t)(((lr + (ls >> 1) * 8) * TS + (ls & 1) * 8) * 2);

    float acc[8][4];
#pragma unroll
    for (int nt = 0; nt < 8; nt++)
#pragma unroll
        for (int q = 0; q < 4; q++) acc[nt][q] = 0.f;

#pragma unroll
    for (int ks = 0; ks < 4; ks++) {
        uint32_t koff = (uint32_t)(ks * 32);
        uint32_t a0, a1, a2, a3;
        ldsm_x4(a0, a1, a2, a3, aB + (uint32_t)(r0 * TS * 2) + koff + a_off);
#pragma unroll
        for (int np = 0; np < 4; np++) {
            uint32_t b0, b1, b2, b3;
            ldsm_x4(b0, b1, b2, b3,
                    bB + (uint32_t)((n0 + np * 16) * TS * 2) + koff + b_off);
            mma_f16(acc[2 * np],     a0, a1, a2, a3, b0, b1);
            mma_f16(acc[2 * np + 1], a0, a1, a2, a3, b2, b3);
        }
    }
    __syncthreads();

    int gid = lane >> 2, tig = lane & 3;
    int rbase = by * 128, cbase = bx * 128;

#pragma unroll 1
    for (int h = 0; h < 2; h++) {
        if ((wid & 1) == h) {
            int rl = r0 + gid;
#pragma unroll
            for (int nt = 0; nt < 8; nt++) {
                int cl = 8 * nt + 2 * tig;
                float2 v0; v0.x = acc[nt][0]; v0.y = acc[nt][1];
                float2 v1; v1.x = acc[nt][2]; v1.y = acc[nt][3];
                *(float2*)&srow[rl * STG_ROW + cl] = v0;
                *(float2*)&srow[(rl + 8) * STG_ROW + cl] = v1;
                if (!diag) {
                    scol[cl * STG_COL + rl]            = acc[nt][0];
                    scol[(cl + 1) * STG_COL + rl]      = acc[nt][1];
                    scol[cl * STG_COL + rl + 8]        = acc[nt][2];
                    scol[(cl + 1) * STG_COL + rl + 8]  = acc[nt][3];
                }
            }
        }
        __syncthreads();
#pragma unroll
        for (int i = 0; i < 4; i++) {
            int lin = tid + i * 512;
            int row = lin >> 4, c4 = (lin & 15) * 4;
            float4 v = *(float4*)&srow[row * STG_ROW + c4];
            stcs4(&C[(size_t)(rbase + row) * NN + cbase + h * 64 + c4], v);
        }
        if (!diag) {
#pragma unroll
            for (int i = 0; i < 4; i++) {
                int lin = tid + i * 512;
                int c = lin >> 5, q = (lin & 31) * 4;
                float4 v = *(float4*)&scol[c * STG_COL + q];
                stcs4(&C[(size_t)(cbase + h * 64 + c) * NN + rbase + q], v);
            }
        }
        __syncthreads();
    }
}

// ---------------- launch ----------------
static float* symf(const void* sym) {
    void* p = nullptr;
    cudaGetSymbolAddress(&p, sym);
    return (float*)p;
}

extern "C" void kernel_launch(void* const* d_in, const int* in_sizes, int n_in,
                              void* d_out, int out_size) {
    const float* h   = (const float*)d_in[0];
    const int*   ei  = (const int*)d_in[1];
    const float* W1  = (const float*)d_in[2];
    const float* b1  = (const float*)d_in[3];
    const float* W2  = (const float*)d_in[4];
    const float* b2  = (const float*)d_in[5];
    const float* Wa1 = (const float*)d_in[6];
    const float* ba1 = (const float*)d_in[7];
    const float* Wa2 = (const float*)d_in[8];
    const float* ba2 = (const float*)d_in[9];
    const float* Ws  = (const float*)d_in[10];
    const float* bs  = (const float*)d_in[11];
    float* out = (float*)d_out;
    int E = in_sizes[1] / 2;

    float*  m     = symf(g_m);
    float*  x     = symf(g_x);
    float*  x2    = symf(g_x2);
    float*  xa    = symf(g_xa);
    float*  aggxa = symf(g_aggxa);
    __half* sh    = (__half*)symf(g_sh);

    float* out_xhat = out + (size_t)N_NODES * (size_t)N_NODES;

    int eb = (E + 255) / 256;

    static cudaStream_t s2 = nullptr;
    static cudaEvent_t ev_fork = nullptr, ev_g512 = nullptr,
                       ev_a2 = nullptr, ev_sst = nullptr;
    if (!s2) {
        cudaFuncSetAttribute(k_sst_mma, cudaFuncAttributeMaxDynamicSharedMemorySize,
                             SM_SST_TOTAL);
        cudaStreamCreateWithFlags(&s2, cudaStreamNonBlocking);
        cudaEventCreateWithFlags(&ev_fork, cudaEventDisableTiming);
        cudaEventCreateWithFlags(&ev_g512, cudaEventDisableTiming);
        cudaEventCreateWithFlags(&ev_a2, cudaEventDisableTiming);
        cudaEventCreateWithFlags(&ev_sst, cudaEventDisableTiming);
    }

    // ---- fork: h@W1 on side stream, CSR build on main stream (independent) ----
    cudaEventRecord(ev_fork, 0);
    cudaStreamWaitEvent(s2, ev_fork, 0);
    k_gemm64<<<dim3(192, 1), 256, 0, s2>>>(h, W1, nullptr, m, nullptr, 512, 64, 0);
    cudaEventRecord(ev_g512, s2);

    k_zero_deg<<<(N_NODES + 255) / 256, 256>>>();
    k_count<<<eb, 256>>>(ei, E);
    k_scan<<<1, 1024>>>();
    k_fill<<<eb, 256>>>(ei, E);

    cudaStreamWaitEvent(0, ev_g512, 0);

    // encoder layer 1: x = relu(agg(h@W1) + b1)
    k_agg<<<1536, 256>>>(m, b1, x, nullptr, 1);
    // encoder layer 2 (agg-then-gemm): x2 = relu(agg(x)@W2 + b2)
    k_agg<<<1536, 256>>>(x, nullptr, m, nullptr, 0);               // A_x -> m
    k_gemm64<<<dim3(192, 1), 256>>>(m, W2, b2, x2, nullptr, 64, 64, 1);
    // shared aggregation for both decoders: A2 = agg(x2) -> m
    k_agg<<<1536, 256>>>(x2, nullptr, m, nullptr, 0);
    cudaEventRecord(ev_a2, 0);

    // ---- side stream: s = relu(A2@Ws + bs) (fp16), then C = s s^T ----
    cudaStreamWaitEvent(s2, ev_a2, 0);
    k_gemm64<<<dim3(192, 1), 256, 0, s2>>>(m, Ws, bs, nullptr, sh, 64, 64, 1);
    k_sst_mma<<<dim3(NTILE, NTILE), 512, SM_SST_TOTAL, s2>>>(sh, out);
    cudaEventRecord(ev_sst, s2);

    // ---- main stream: attribute decoder ----
    k_gemm64<<<dim3(192, 1), 256>>>(m, Wa1, ba1, xa, nullptr, 64, 64, 1);
    k_agg<<<1536, 256>>>(xa, nullptr, aggxa, nullptr, 0);
    k_gemm64<<<dim3(192, 8), 256>>>(aggxa, Wa2, ba2, out_xhat, nullptr, 64, 512, 1);

    // join
    cudaStreamWaitEvent(0, ev_sst, 0);
}